// round 2
// baseline (speedup 1.0000x reference)
#include <cuda_runtime.h>
#include <cuda_bf16.h>
#include <math.h>

#define NU 50000
#define NI 100000
#define NN 150000
#define DD 64
#define BB 4096
#define EMAX 3150000

// ---------------- device scratch (static: no allocations allowed) ----------
__device__ float  d_deg[NN];           // degree, then d^-0.5 in place
__device__ float  d_gv[EMAX];          // per-edge g values
__device__ float  d_cur[NN * DD];
__device__ float  d_nxt[NN * DD];
__device__ float  d_acc[NN * DD];
__device__ float  d_genN[2 * BB * DD]; // normalized gen_emb rows (user side, item side)
__device__ float  d_intN[2 * BB * DD]; // normalized intent rows
__device__ float  d_negS[2 * BB];      // InfoNCE denominators
__device__ float  d_posS[2 * BB];      // diagonal dots
__device__ double d_sums[4];           // 0: kl, 1: bpr, 2: emb

__device__ __forceinline__ float softplus_f(float x) {
    return x > 0.f ? x + log1pf(expf(-x)) : log1pf(expf(x));
}

__device__ __forceinline__ void red4(float4* p, float x, float y, float z, float w) {
    asm volatile("red.global.add.v4.f32 [%0], {%1,%2,%3,%4};"
                 :: "l"(p), "f"(x), "f"(y), "f"(z), "f"(w) : "memory");
}

// ---------------- kernels --------------------------------------------------
__global__ void k_init() {
    int i = blockIdx.x * blockDim.x + threadIdx.x;
    if (i < NN) d_deg[i] = 0.f;
    if (i < 4)  d_sums[i] = 0.0;
}

__global__ void k_deg(const int* __restrict__ h, int E) {
    int e = blockIdx.x * blockDim.x + threadIdx.x;
    if (e < E) atomicAdd(&d_deg[h[e]], 1.0f);
}

__global__ void k_dinv() {
    int i = blockIdx.x * blockDim.x + threadIdx.x;
    if (i < NN) d_deg[i] = rsqrtf(d_deg[i]);
}

__global__ void k_gvals(const int* __restrict__ h, const int* __restrict__ t, int E) {
    int e = blockIdx.x * blockDim.x + threadIdx.x;
    if (e < E) d_gv[e] = d_deg[h[e]] * d_deg[t[e]];
}

__global__ void k_copy(const float4* __restrict__ uemb, const float4* __restrict__ iemb) {
    int i = blockIdx.x * blockDim.x + threadIdx.x;
    if (i < NN * 16) {
        float4 v = (i < NU * 16) ? uemb[i] : iemb[i - NU * 16];
        ((float4*)d_cur)[i] = v;
        ((float4*)d_acc)[i] = v;
        ((float4*)d_nxt)[i] = make_float4(0.f, 0.f, 0.f, 0.f);
    }
}

// dir==0: cur -> nxt ; dir==1: nxt -> cur. 16 threads (float4 chunks) per edge.
__global__ void k_scatter(const int* __restrict__ h, const int* __restrict__ t, int E, int dir) {
    int tid = blockIdx.x * blockDim.x + threadIdx.x;
    int e = tid >> 4;
    if (e >= E) return;
    int c = tid & 15;
    const float4* src = dir ? (const float4*)d_nxt : (const float4*)d_cur;
    float4*       dst = dir ? (float4*)d_cur       : (float4*)d_nxt;
    int   hh = __ldg(h + e);
    int   tt = __ldg(t + e);
    float g  = d_gv[e];
    float4 v = __ldg(&src[tt * 16 + c]);
    red4(&dst[hh * 16 + c], g * v.x, g * v.y, g * v.z, g * v.w);
}

// mode 0: acc += nxt, zero cur ; mode 1: acc += cur, zero nxt ; mode 2: acc += nxt
__global__ void k_accum(int mode) {
    int i = blockIdx.x * blockDim.x + threadIdx.x;
    if (i >= NN * 16) return;
    float4* acc = (float4*)d_acc;
    float4* cur = (float4*)d_cur;
    float4* nxt = (float4*)d_nxt;
    float4 v = (mode == 1) ? cur[i] : nxt[i];
    float4 a = acc[i];
    a.x += v.x; a.y += v.y; a.z += v.z; a.w += v.w;
    acc[i] = a;
    if (mode == 0) cur[i] = make_float4(0.f, 0.f, 0.f, 0.f);
    else if (mode == 1) nxt[i] = make_float4(0.f, 0.f, 0.f, 0.f);
}

// KL over all N rows: std = softplus(acc[:, :32]) @ W^T + b + 1e-8
__global__ void k_kl(const float* __restrict__ lin_w, const float* __restrict__ lin_b) {
    __shared__ float Wt[32 * 64];     // transposed: Wt[t*64 + d]
    __shared__ float Bsh[64];
    __shared__ float warpsum[8];
    int tid = threadIdx.x;
    for (int i = tid; i < 2048; i += 256) {
        int d = i >> 5, tt = i & 31;
        Wt[tt * 64 + d] = lin_w[i];
    }
    if (tid < 64) Bsh[tid] = lin_b[tid];
    __syncthreads();
    int w = tid >> 5, lane = tid & 31;
    float local = 0.f;
    for (int it = 0; it < 4; it++) {
        int row = blockIdx.x * 32 + w * 4 + it;
        if (row < NN) {
            float a0 = d_acc[row * 64 + lane];
            float a1 = d_acc[row * 64 + 32 + lane];
            float sp = softplus_f(a0);       // lane t holds sp_t
            float s0 = 0.f, s1 = 0.f;
            #pragma unroll
            for (int tt = 0; tt < 32; tt++) {
                float spt = __shfl_sync(0xffffffffu, sp, tt);
                s0 += spt * Wt[tt * 64 + lane];
                s1 += spt * Wt[tt * 64 + 32 + lane];
            }
            s0 += Bsh[lane] + 1e-8f;
            s1 += Bsh[lane + 32] + 1e-8f;
            float k0 = -0.5f * (1.f + 2.f * s0 - a0 * a0 - expf(2.f * s0));
            float k1 = -0.5f * (1.f + 2.f * s1 - a1 * a1 - expf(2.f * s1));
            if (!isfinite(k0)) k0 = 0.f;
            if (!isfinite(k1)) k1 = 0.f;
            local += k0 + k1;
        }
    }
    #pragma unroll
    for (int o = 16; o; o >>= 1) local += __shfl_xor_sync(0xffffffffu, local, o);
    if (lane == 0) warpsum[w] = local;
    __syncthreads();
    if (tid == 0) {
        float s = 0.f;
        for (int i = 0; i < 8; i++) s += warpsum[i];
        atomicAdd(&d_sums[0], (double)s);
    }
}

__global__ void k_bpr_emb(const float* __restrict__ ue, const float* __restrict__ ie,
                          const int* __restrict__ users, const int* __restrict__ pos,
                          const int* __restrict__ neg) {
    __shared__ float sb[8], se[8];
    int w = threadIdx.x >> 5, lane = threadIdx.x & 31;
    int b = blockIdx.x * 8 + w;
    float bpr = 0.f, emb = 0.f;
    {
        int u = users[b], pi = pos[b], ni = neg[b];
        float u0 = d_acc[u * 64 + lane],            u1 = d_acc[u * 64 + 32 + lane];
        float p0 = d_acc[(NU + pi) * 64 + lane],    p1 = d_acc[(NU + pi) * 64 + 32 + lane];
        float n0 = d_acc[(NU + ni) * 64 + lane],    n1 = d_acc[(NU + ni) * 64 + 32 + lane];
        float dsc = (u0 * n0 + u1 * n1) - (u0 * p0 + u1 * p1);
        float r0 = ue[u * 64 + lane],  r1 = ue[u * 64 + 32 + lane];
        float q0 = ie[pi * 64 + lane], q1 = ie[pi * 64 + 32 + lane];
        float m0 = ie[ni * 64 + lane], m1 = ie[ni * 64 + 32 + lane];
        float sq = r0 * r0 + r1 * r1 + q0 * q0 + q1 * q1 + m0 * m0 + m1 * m1;
        #pragma unroll
        for (int o = 16; o; o >>= 1) {
            dsc += __shfl_xor_sync(0xffffffffu, dsc, o);
            sq  += __shfl_xor_sync(0xffffffffu, sq, o);
        }
        if (lane == 0) { bpr = softplus_f(dsc); emb = sq; }
    }
    if (lane == 0) { sb[w] = bpr; se[w] = emb; }
    __syncthreads();
    if (threadIdx.x == 0) {
        float s1 = 0.f, s2 = 0.f;
        for (int i = 0; i < 8; i++) { s1 += sb[i]; s2 += se[i]; }
        atomicAdd(&d_sums[1], (double)s1);
        atomicAdd(&d_sums[2], (double)s2);
    }
}

// Build normalized gen_emb row + normalized intent row for each sampled index.
// grid (4096, 2), 128 threads. s=0: users (ua/user_intent), s=1: pos_items (ia/item_intent).
__global__ void k_build_cl(const float* __restrict__ u_int_w, const float* __restrict__ i_int_w,
                           const float* __restrict__ lin_w, const float* __restrict__ lin_b,
                           const float* __restrict__ eps,
                           const int* __restrict__ users, const int* __restrict__ pos) {
    __shared__ float sI[64 * 129];
    __shared__ float sA[64];
    __shared__ float sSp[32];
    __shared__ float sP[128];
    __shared__ float sRed[128];
    __shared__ float sG[64], sO[64];
    int tid = threadIdx.x;
    int b = blockIdx.x, s = blockIdx.y;
    int r = s ? (NU + pos[b]) : users[b];
    const float* intent = s ? i_int_w : u_int_w;

    for (int i = tid; i < 8192; i += 128)
        sI[(i >> 7) * 129 + (i & 127)] = intent[i];
    if (tid < 64) sA[tid] = d_acc[r * 64 + tid];
    __syncthreads();
    if (tid < 32) sSp[tid] = softplus_f(sA[tid]);

    // logits_k = a . intent[:,k]   (tid = k, 0..127)
    float lg = 0.f;
    #pragma unroll 8
    for (int d = 0; d < 64; d++) lg += sA[d] * sI[d * 129 + tid];

    sRed[tid] = lg; __syncthreads();
    for (int o = 64; o; o >>= 1) { if (tid < o) sRed[tid] = fmaxf(sRed[tid], sRed[tid + o]); __syncthreads(); }
    float mx = sRed[0]; __syncthreads();
    float pe = expf(lg - mx);
    sRed[tid] = pe; __syncthreads();
    for (int o = 64; o; o >>= 1) { if (tid < o) sRed[tid] += sRed[tid + o]; __syncthreads(); }
    float psum = sRed[0];
    sP[tid] = pe / psum;
    __syncthreads();

    float genv = 0.f, ov = 0.f;
    if (tid < 64) {
        #pragma unroll 8
        for (int k = 0; k < 128; k++) ov += sP[k] * sI[tid * 129 + k];
        float sd = 1e-8f + lin_b[tid];
        #pragma unroll
        for (int tt = 0; tt < 32; tt++) sd += sSp[tt] * lin_w[tid * 32 + tt];
        genv = sA[tid] + eps[r * 64 + tid] * sd;
        sG[tid] = genv * genv;
        sO[tid] = ov * ov;
    }
    __syncthreads();
    for (int o = 32; o; o >>= 1) { if (tid < o) { sG[tid] += sG[tid + o]; sO[tid] += sO[tid + o]; } __syncthreads(); }
    float gn = rsqrtf(sG[0]), on = rsqrtf(sO[0]);
    if (tid < 64) {
        float gnv = genv * gn, onv = ov * on;
        d_genN[(s * BB + b) * 64 + tid] = gnv;
        d_intN[(s * BB + b) * 64 + tid] = onv;
        sRed[tid] = gnv * onv;
    } else sRed[tid] = 0.f;
    __syncthreads();
    for (int o = 64; o; o >>= 1) { if (tid < o) sRed[tid] += sRed[tid + o]; __syncthreads(); }
    if (tid == 0) d_posS[s * BB + b] = sRed[0];
}

// neg_b = sum_c exp(dot(A_b, B_c)/T). grid (64, 2), block 256 (16x16), 64 rows/block.
__global__ void k_infonce() {
    __shared__ float As[64][65];
    __shared__ float Bs[64][65];
    __shared__ float Rd[64][17];
    int s = blockIdx.y;
    int r0 = blockIdx.x * 64;
    const float* A  = d_genN + s * BB * 64;
    const float* Bm = d_intN + s * BB * 64;
    int tid = threadIdx.x;
    for (int i = tid; i < 4096; i += 256)
        As[i >> 6][i & 63] = A[(r0 + (i >> 6)) * 64 + (i & 63)];
    int tx = tid & 15, ty = tid >> 4;
    float rowAcc[4] = {0.f, 0.f, 0.f, 0.f};
    for (int ct = 0; ct < BB / 64; ct++) {
        __syncthreads();
        for (int i = tid; i < 4096; i += 256)
            Bs[i >> 6][i & 63] = Bm[(ct * 64 + (i >> 6)) * 64 + (i & 63)];
        __syncthreads();
        float am[4][4] = {};
        #pragma unroll 16
        for (int k = 0; k < 64; k++) {
            float a[4], bb[4];
            #pragma unroll
            for (int i = 0; i < 4; i++) a[i] = As[ty * 4 + i][k];
            #pragma unroll
            for (int j = 0; j < 4; j++) bb[j] = Bs[tx * 4 + j][k];
            #pragma unroll
            for (int i = 0; i < 4; i++)
                #pragma unroll
                for (int j = 0; j < 4; j++) am[i][j] += a[i] * bb[j];
        }
        #pragma unroll
        for (int i = 0; i < 4; i++) {
            float tacc = 0.f;
            #pragma unroll
            for (int j = 0; j < 4; j++) tacc += __expf(am[i][j] * 5.0f);
            rowAcc[i] += tacc;
        }
    }
    __syncthreads();
    #pragma unroll
    for (int i = 0; i < 4; i++) Rd[ty * 4 + i][tx] = rowAcc[i];
    __syncthreads();
    if (tid < 64) {
        float sm = 0.f;
        for (int x = 0; x < 16; x++) sm += Rd[tid][x];
        d_negS[s * BB + r0 + tid] = sm;
    }
}

__global__ void k_final(const float* __restrict__ ui, const float* __restrict__ ii,
                        float* __restrict__ out) {
    __shared__ double sh[256];
    __shared__ double sh2[256];
    int tid = threadIdx.x;
    double isum = 0.0, clsum = 0.0;
    for (int i = tid; i < 8192; i += 256) {
        float a = ui[i], b2 = ii[i];
        isum += (double)a * a + (double)b2 * b2;
    }
    for (int i = tid; i < 2 * BB; i += 256) {
        float ng = d_negS[i];
        float p  = expf(d_posS[i] * 5.0f);   // 1/TEMP = 5
        clsum += -(double)logf(p / (ng + 1e-8f) + 1e-8f);
    }
    sh[tid] = isum; sh2[tid] = clsum;
    __syncthreads();
    for (int o = 128; o; o >>= 1) {
        if (tid < o) { sh[tid] += sh[tid + o]; sh2[tid] += sh2[tid + o]; }
        __syncthreads();
    }
    if (tid == 0) {
        double kl = d_sums[0], bpr = d_sums[1], emb = d_sums[2];
        out[0] = (float)(bpr / 4096.0 + 0.01 * (kl / 150000.0)); // gen_loss
        out[1] = (float)(0.1 * (sh2[0] / 4096.0));               // cl_loss
        out[2] = (float)(1e-5 * emb);                            // emb_loss
        out[3] = (float)(1e-5 * sh[0]);                          // int_loss
    }
}

// ---------------- launch ---------------------------------------------------
extern "C" void kernel_launch(void* const* d_in, const int* in_sizes, int n_in,
                              void* d_out, int out_size) {
    (void)n_in; (void)out_size;
    const float* user_emb = (const float*)d_in[0];
    const float* item_emb = (const float*)d_in[1];
    const float* user_int = (const float*)d_in[2];
    const float* item_int = (const float*)d_in[3];
    const float* lin_w    = (const float*)d_in[4];
    const float* lin_b    = (const float*)d_in[5];
    const float* eps      = (const float*)d_in[6];
    const int*   h        = (const int*)d_in[7];
    const int*   t        = (const int*)d_in[8];
    const int*   users    = (const int*)d_in[9];
    const int*   pos      = (const int*)d_in[10];
    const int*   neg      = (const int*)d_in[11];
    int E = in_sizes[7];
    float* out = (float*)d_out;

    k_init<<<(NN + 255) / 256, 256>>>();
    k_deg<<<(E + 255) / 256, 256>>>(h, E);
    k_dinv<<<(NN + 255) / 256, 256>>>();
    k_gvals<<<(E + 255) / 256, 256>>>(h, t, E);
    k_copy<<<(NN * 16 + 255) / 256, 256>>>((const float4*)user_emb, (const float4*)item_emb);

    int sb = (int)(((long long)E * 16 + 255) / 256);
    int nb = (NN * 16 + 255) / 256;
    k_scatter<<<sb, 256>>>(h, t, E, 0);   // cur -> nxt
    k_accum<<<nb, 256>>>(0);              // acc += nxt, cur = 0
    k_scatter<<<sb, 256>>>(h, t, E, 1);   // nxt -> cur
    k_accum<<<nb, 256>>>(1);              // acc += cur, nxt = 0
    k_scatter<<<sb, 256>>>(h, t, E, 0);   // cur -> nxt
    k_accum<<<nb, 256>>>(2);              // acc += nxt

    k_kl<<<(NN + 31) / 32, 256>>>(lin_w, lin_b);
    k_bpr_emb<<<BB / 8, 256>>>(user_emb, item_emb, users, pos, neg);
    k_build_cl<<<dim3(BB, 2), 128>>>(user_int, item_int, lin_w, lin_b, eps, users, pos);
    k_infonce<<<dim3(64, 2), 256>>>();
    k_final<<<1, 256>>>(user_int, item_int, out);
}

// round 3
// speedup vs baseline: 1.0977x; 1.0977x over previous
#include <cuda_runtime.h>
#include <cuda_bf16.h>
#include <math.h>

#define NU 50000
#define NI 100000
#define NN 150000
#define DD 64
#define BB 4096
#define EMAX 3150000

// ---------------- device scratch -------------------------------------------
__device__ float  d_deg[NN];            // d^-0.5
__device__ int    d_cnt[NN];            // degree counts, then bin cursors
__device__ int    d_rowptr[NN + 1];
__device__ int2   d_epack[EMAX];        // {t, g as float bits} CSR-sorted
__device__ float  d_cur[NN * DD];
__device__ float  d_nxt[NN * DD];
__device__ float  d_acc[NN * DD];
__device__ float  d_genN[2 * BB * DD];
__device__ float  d_intN[2 * BB * DD];
__device__ float  d_negS[2 * BB];
__device__ float  d_posS[2 * BB];
__device__ double d_sums[4];            // 0: kl, 1: bpr, 2: emb

__device__ __forceinline__ float softplus_f(float x) {
    return x > 0.f ? x + log1pf(expf(-x)) : log1pf(expf(x));
}

// ---------------- CSR build ------------------------------------------------
__global__ void k_init() {
    int i = blockIdx.x * blockDim.x + threadIdx.x;
    if (i < NN) d_cnt[i] = 0;
    if (i < 2 * BB) d_negS[i] = 0.f;
    if (i < 4) d_sums[i] = 0.0;
}

__global__ void k_count(const int* __restrict__ h, int E) {
    int e = blockIdx.x * blockDim.x + threadIdx.x;
    if (e < E) atomicAdd(&d_cnt[h[e]], 1);
}

// single block, 1024 threads: exclusive scan of d_cnt -> d_rowptr, cursor copy,
// and d_deg = rsqrt(count)
__global__ void k_scan(int E) {
    __shared__ int ss[1024];
    const int C = 147;                 // 1024*147 >= NN
    int tid = threadIdx.x;
    int base = tid * C;
    int s = 0;
    #pragma unroll 4
    for (int i = 0; i < C; i++) {
        int idx = base + i;
        if (idx < NN) s += d_cnt[idx];
    }
    ss[tid] = s;
    __syncthreads();
    for (int o = 1; o < 1024; o <<= 1) {
        int v = ss[tid];
        if (tid >= o) v += ss[tid - o];
        __syncthreads();
        ss[tid] = v;
        __syncthreads();
    }
    int run = ss[tid] - s;             // exclusive prefix
    for (int i = 0; i < C; i++) {
        int idx = base + i;
        if (idx < NN) {
            int c = d_cnt[idx];
            d_rowptr[idx] = run;
            d_cnt[idx] = run;          // cursor for binning
            d_deg[idx] = rsqrtf((float)c);
            run += c;
        }
    }
    if (tid == 1023) d_rowptr[NN] = run;
}

__global__ void k_bin(const int* __restrict__ h, const int* __restrict__ t, int E) {
    int e = blockIdx.x * blockDim.x + threadIdx.x;
    if (e >= E) return;
    int n = h[e], tt = t[e];
    int p = atomicAdd(&d_cnt[n], 1);
    d_epack[p] = make_int2(tt, __float_as_int(d_deg[n] * d_deg[tt]));
}

__global__ void k_copy(const float4* __restrict__ uemb, const float4* __restrict__ iemb) {
    int i = blockIdx.x * blockDim.x + threadIdx.x;
    if (i < NN * 16) {
        float4 v = (i < NU * 16) ? uemb[i] : iemb[i - NU * 16];
        ((float4*)d_cur)[i] = v;
        ((float4*)d_acc)[i] = v;
    }
}

// ---------------- pull gather: one warp per node, fused acc += -------------
__global__ void k_gather(int dir) {
    int w = (blockIdx.x * blockDim.x + threadIdx.x) >> 5;
    if (w >= NN) return;
    int lane = threadIdx.x & 31;
    const float* __restrict__ src = dir ? d_nxt : d_cur;
    float* __restrict__ dst = dir ? d_cur : d_nxt;
    int beg = __ldg(&d_rowptr[w]);
    int end = __ldg(&d_rowptr[w + 1]);
    float v0 = 0.f, v1 = 0.f;
    int e = beg;
    int2 p0;
    if (e < end) p0 = __ldg(&d_epack[e]);
    while (e < end) {
        int2 p = p0;
        ++e;
        if (e < end) p0 = __ldg(&d_epack[e]);   // pipeline next edge record
        float g = __int_as_float(p.y);
        const float* s = src + (size_t)p.x * 64;
        v0 += g * __ldg(s + lane);
        v1 += g * __ldg(s + 32 + lane);
    }
    size_t o = (size_t)w * 64 + lane;
    dst[o] = v0;
    dst[o + 32] = v1;
    d_acc[o] += v0;
    d_acc[o + 32] += v1;
}

// ---------------- KL over all rows -----------------------------------------
__global__ void k_kl(const float* __restrict__ lin_w, const float* __restrict__ lin_b) {
    __shared__ float Wt[32 * 64];
    __shared__ float Bsh[64];
    __shared__ float warpsum[8];
    int tid = threadIdx.x;
    for (int i = tid; i < 2048; i += 256) {
        int d = i >> 5, tt = i & 31;
        Wt[tt * 64 + d] = lin_w[i];
    }
    if (tid < 64) Bsh[tid] = lin_b[tid];
    __syncthreads();
    int w = tid >> 5, lane = tid & 31;
    float local = 0.f;
    for (int it = 0; it < 4; it++) {
        int row = blockIdx.x * 32 + w * 4 + it;
        if (row < NN) {
            float a0 = d_acc[row * 64 + lane];
            float a1 = d_acc[row * 64 + 32 + lane];
            float sp = softplus_f(a0);
            float s0 = 0.f, s1 = 0.f;
            #pragma unroll
            for (int tt = 0; tt < 32; tt++) {
                float spt = __shfl_sync(0xffffffffu, sp, tt);
                s0 += spt * Wt[tt * 64 + lane];
                s1 += spt * Wt[tt * 64 + 32 + lane];
            }
            s0 += Bsh[lane] + 1e-8f;
            s1 += Bsh[lane + 32] + 1e-8f;
            float k0 = -0.5f * (1.f + 2.f * s0 - a0 * a0 - expf(2.f * s0));
            float k1 = -0.5f * (1.f + 2.f * s1 - a1 * a1 - expf(2.f * s1));
            if (!isfinite(k0)) k0 = 0.f;
            if (!isfinite(k1)) k1 = 0.f;
            local += k0 + k1;
        }
    }
    #pragma unroll
    for (int o = 16; o; o >>= 1) local += __shfl_xor_sync(0xffffffffu, local, o);
    if (lane == 0) warpsum[w] = local;
    __syncthreads();
    if (tid == 0) {
        float s = 0.f;
        for (int i = 0; i < 8; i++) s += warpsum[i];
        atomicAdd(&d_sums[0], (double)s);
    }
}

__global__ void k_bpr_emb(const float* __restrict__ ue, const float* __restrict__ ie,
                          const int* __restrict__ users, const int* __restrict__ pos,
                          const int* __restrict__ neg) {
    __shared__ float sb[8], se[8];
    int w = threadIdx.x >> 5, lane = threadIdx.x & 31;
    int b = blockIdx.x * 8 + w;
    float bpr = 0.f, emb = 0.f;
    {
        int u = users[b], pi = pos[b], ni = neg[b];
        float u0 = d_acc[u * 64 + lane],         u1 = d_acc[u * 64 + 32 + lane];
        float p0 = d_acc[(NU + pi) * 64 + lane], p1 = d_acc[(NU + pi) * 64 + 32 + lane];
        float n0 = d_acc[(NU + ni) * 64 + lane], n1 = d_acc[(NU + ni) * 64 + 32 + lane];
        float dsc = (u0 * n0 + u1 * n1) - (u0 * p0 + u1 * p1);
        float r0 = ue[u * 64 + lane],  r1 = ue[u * 64 + 32 + lane];
        float q0 = ie[pi * 64 + lane], q1 = ie[pi * 64 + 32 + lane];
        float m0 = ie[ni * 64 + lane], m1 = ie[ni * 64 + 32 + lane];
        float sq = r0 * r0 + r1 * r1 + q0 * q0 + q1 * q1 + m0 * m0 + m1 * m1;
        #pragma unroll
        for (int o = 16; o; o >>= 1) {
            dsc += __shfl_xor_sync(0xffffffffu, dsc, o);
            sq  += __shfl_xor_sync(0xffffffffu, sq, o);
        }
        if (lane == 0) { bpr = softplus_f(dsc); emb = sq; }
    }
    if (lane == 0) { sb[w] = bpr; se[w] = emb; }
    __syncthreads();
    if (threadIdx.x == 0) {
        float s1 = 0.f, s2 = 0.f;
        for (int i = 0; i < 8; i++) { s1 += sb[i]; s2 += se[i]; }
        atomicAdd(&d_sums[1], (double)s1);
        atomicAdd(&d_sums[2], (double)s2);
    }
}

// ---------------- build normalized CL rows ---------------------------------
__global__ void k_build_cl(const float* __restrict__ u_int_w, const float* __restrict__ i_int_w,
                           const float* __restrict__ lin_w, const float* __restrict__ lin_b,
                           const float* __restrict__ eps,
                           const int* __restrict__ users, const int* __restrict__ pos) {
    __shared__ float sI[64 * 129];
    __shared__ float sA[64];
    __shared__ float sSp[32];
    __shared__ float sP[128];
    __shared__ float sRed[128];
    __shared__ float sG[64], sO[64];
    int tid = threadIdx.x;
    int b = blockIdx.x, s = blockIdx.y;
    int r = s ? (NU + pos[b]) : users[b];
    const float* intent = s ? i_int_w : u_int_w;

    for (int i = tid; i < 8192; i += 128)
        sI[(i >> 7) * 129 + (i & 127)] = intent[i];
    if (tid < 64) sA[tid] = d_acc[r * 64 + tid];
    __syncthreads();
    if (tid < 32) sSp[tid] = softplus_f(sA[tid]);

    float lg = 0.f;
    #pragma unroll 8
    for (int d = 0; d < 64; d++) lg += sA[d] * sI[d * 129 + tid];

    sRed[tid] = lg; __syncthreads();
    for (int o = 64; o; o >>= 1) { if (tid < o) sRed[tid] = fmaxf(sRed[tid], sRed[tid + o]); __syncthreads(); }
    float mx = sRed[0]; __syncthreads();
    float pe = expf(lg - mx);
    sRed[tid] = pe; __syncthreads();
    for (int o = 64; o; o >>= 1) { if (tid < o) sRed[tid] += sRed[tid + o]; __syncthreads(); }
    float psum = sRed[0];
    sP[tid] = pe / psum;
    __syncthreads();

    float genv = 0.f, ov = 0.f;
    if (tid < 64) {
        #pragma unroll 8
        for (int k = 0; k < 128; k++) ov += sP[k] * sI[tid * 129 + k];
        float sd = 1e-8f + lin_b[tid];
        #pragma unroll
        for (int tt = 0; tt < 32; tt++) sd += sSp[tt] * lin_w[tid * 32 + tt];
        genv = sA[tid] + eps[r * 64 + tid] * sd;
        sG[tid] = genv * genv;
        sO[tid] = ov * ov;
    }
    __syncthreads();
    for (int o = 32; o; o >>= 1) { if (tid < o) { sG[tid] += sG[tid + o]; sO[tid] += sO[tid + o]; } __syncthreads(); }
    float gn = rsqrtf(sG[0]), on = rsqrtf(sO[0]);
    if (tid < 64) {
        float gnv = genv * gn, onv = ov * on;
        d_genN[(s * BB + b) * 64 + tid] = gnv;
        d_intN[(s * BB + b) * 64 + tid] = onv;
        sRed[tid] = gnv * onv;
    } else sRed[tid] = 0.f;
    __syncthreads();
    for (int o = 64; o; o >>= 1) { if (tid < o) sRed[tid] += sRed[tid + o]; __syncthreads(); }
    if (tid == 0) d_posS[s * BB + b] = sRed[0];
}

// ---------------- InfoNCE denominators: FMA-blocked GEMM-like --------------
// grid (64 rowtiles, 4 colgroups, 2 sides), block 256 (16x16), 4x4 per thread.
// k-major smem tiles + float4 LDS -> 2 LDS.128 per 16 FMA.
#define NCG 4
__global__ void k_infonce() {
    __shared__ __align__(16) float As[64][68];  // [k][row]
    __shared__ __align__(16) float Bs[64][68];  // [k][col]
    __shared__ float Rd[64][17];
    int s = blockIdx.z;
    int r0 = blockIdx.x * 64;
    int cg = blockIdx.y;
    const float* __restrict__ A  = d_genN + (size_t)s * BB * 64;
    const float* __restrict__ Bm = d_intN + (size_t)s * BB * 64;
    int tid = threadIdx.x;
    int tx = tid & 15, ty = tid >> 4;

    for (int i = tid; i < 4096; i += 256) {
        int r = i >> 6, k = i & 63;
        As[k][r] = A[(size_t)(r0 + r) * 64 + k];
    }

    float rowAcc[4] = {0.f, 0.f, 0.f, 0.f};
    for (int ct = 0; ct < BB / 64 / NCG; ct++) {
        int c0 = (cg * (BB / 64 / NCG) + ct) * 64;
        __syncthreads();
        for (int i = tid; i < 4096; i += 256) {
            int r = i >> 6, k = i & 63;
            Bs[k][r] = Bm[(size_t)(c0 + r) * 64 + k];
        }
        __syncthreads();
        float am[4][4] = {};
        #pragma unroll 16
        for (int k = 0; k < 64; k++) {
            float4 a = *(const float4*)&As[k][ty * 4];
            float4 b = *(const float4*)&Bs[k][tx * 4];
            am[0][0] += a.x * b.x; am[0][1] += a.x * b.y; am[0][2] += a.x * b.z; am[0][3] += a.x * b.w;
            am[1][0] += a.y * b.x; am[1][1] += a.y * b.y; am[1][2] += a.y * b.z; am[1][3] += a.y * b.w;
            am[2][0] += a.z * b.x; am[2][1] += a.z * b.y; am[2][2] += a.z * b.z; am[2][3] += a.z * b.w;
            am[3][0] += a.w * b.x; am[3][1] += a.w * b.y; am[3][2] += a.w * b.z; am[3][3] += a.w * b.w;
        }
        #pragma unroll
        for (int i = 0; i < 4; i++) {
            float tacc = 0.f;
            #pragma unroll
            for (int j = 0; j < 4; j++) tacc += __expf(am[i][j] * 5.0f);
            rowAcc[i] += tacc;
        }
    }
    __syncthreads();
    #pragma unroll
    for (int i = 0; i < 4; i++) Rd[ty * 4 + i][tx] = rowAcc[i];
    __syncthreads();
    if (tid < 64) {
        float sm = 0.f;
        #pragma unroll
        for (int x = 0; x < 16; x++) sm += Rd[tid][x];
        atomicAdd(&d_negS[s * BB + r0 + tid], sm);
    }
}

__global__ void k_final(const float* __restrict__ ui, const float* __restrict__ ii,
                        float* __restrict__ out) {
    __shared__ double sh[256];
    __shared__ double sh2[256];
    int tid = threadIdx.x;
    double isum = 0.0, clsum = 0.0;
    for (int i = tid; i < 8192; i += 256) {
        float a = ui[i], b2 = ii[i];
        isum += (double)a * a + (double)b2 * b2;
    }
    for (int i = tid; i < 2 * BB; i += 256) {
        float ng = d_negS[i];
        float p  = expf(d_posS[i] * 5.0f);
        clsum += -(double)logf(p / (ng + 1e-8f) + 1e-8f);
    }
    sh[tid] = isum; sh2[tid] = clsum;
    __syncthreads();
    for (int o = 128; o; o >>= 1) {
        if (tid < o) { sh[tid] += sh[tid + o]; sh2[tid] += sh2[tid + o]; }
        __syncthreads();
    }
    if (tid == 0) {
        double kl = d_sums[0], bpr = d_sums[1], emb = d_sums[2];
        out[0] = (float)(bpr / 4096.0 + 0.01 * (kl / 150000.0));
        out[1] = (float)(0.1 * (sh2[0] / 4096.0));
        out[2] = (float)(1e-5 * emb);
        out[3] = (float)(1e-5 * sh[0]);
    }
}

// ---------------- launch ---------------------------------------------------
extern "C" void kernel_launch(void* const* d_in, const int* in_sizes, int n_in,
                              void* d_out, int out_size) {
    (void)n_in; (void)out_size;
    const float* user_emb = (const float*)d_in[0];
    const float* item_emb = (const float*)d_in[1];
    const float* user_int = (const float*)d_in[2];
    const float* item_int = (const float*)d_in[3];
    const float* lin_w    = (const float*)d_in[4];
    const float* lin_b    = (const float*)d_in[5];
    const float* eps      = (const float*)d_in[6];
    const int*   h        = (const int*)d_in[7];
    const int*   t        = (const int*)d_in[8];
    const int*   users    = (const int*)d_in[9];
    const int*   pos      = (const int*)d_in[10];
    const int*   neg      = (const int*)d_in[11];
    int E = in_sizes[7];
    float* out = (float*)d_out;

    k_init<<<(NN + 255) / 256, 256>>>();
    k_count<<<(E + 255) / 256, 256>>>(h, E);
    k_scan<<<1, 1024>>>(E);
    k_bin<<<(E + 255) / 256, 256>>>(h, t, E);
    k_copy<<<(NN * 16 + 255) / 256, 256>>>((const float4*)user_emb, (const float4*)item_emb);

    int gb = (NN * 32 + 255) / 256;   // warp per node
    k_gather<<<gb, 256>>>(0);         // cur -> nxt, acc += nxt
    k_gather<<<gb, 256>>>(1);         // nxt -> cur, acc += cur
    k_gather<<<gb, 256>>>(0);         // cur -> nxt, acc += nxt

    k_kl<<<(NN + 31) / 32, 256>>>(lin_w, lin_b);
    k_bpr_emb<<<BB / 8, 256>>>(user_emb, item_emb, users, pos, neg);
    k_build_cl<<<dim3(BB, 2), 128>>>(user_int, item_int, lin_w, lin_b, eps, users, pos);
    k_infonce<<<dim3(64, NCG, 2), 256>>>();
    k_final<<<1, 256>>>(user_int, item_int, out);
}

// round 4
// speedup vs baseline: 1.4697x; 1.3389x over previous
#include <cuda_runtime.h>
#include <cuda_bf16.h>
#include <math.h>

#define NU 50000
#define NI 100000
#define NN 150000
#define DD 64
#define BB 4096
#define EMAX 3150000
#define NBLK 586            // ceil(NN/256)

// ---------------- device scratch -------------------------------------------
__device__ float  d_deg[NN];
__device__ int    d_cnt[NN];            // counts, then bin cursors
__device__ int    d_bsum[1024];
__device__ int    d_rowptr[NN + 1];
__device__ int2   d_epack[EMAX];        // {t, g bits}
__device__ float  d_cur[NN * DD];
__device__ float  d_nxt[NN * DD];
__device__ float  d_acc[NN * DD];
__device__ float  d_genN[2 * BB * DD];
__device__ float  d_intN[2 * BB * DD];
__device__ float  d_negS[2 * BB];
__device__ float  d_posS[2 * BB];
__device__ double d_sums[4];            // 0: kl, 1: bpr, 2: emb

__device__ __forceinline__ float softplus_f(float x) {
    return x > 0.f ? x + log1pf(expf(-x)) : log1pf(expf(x));
}

#define FFMA2(d, a, b) asm("fma.rn.f32x2 %0, %1, %2, %0;" : "+l"(d) : "l"(a), "l"(b))
#define UNPACK2(lo, hi, v) asm("mov.b64 {%0,%1}, %2;" : "=f"(lo), "=f"(hi) : "l"(v))

// ---------------- CSR build ------------------------------------------------
__global__ void k_init() {
    int i = blockIdx.x * blockDim.x + threadIdx.x;
    if (i < NN) d_cnt[i] = 0;
    if (i < 2 * BB) d_negS[i] = 0.f;
    if (i < 4) d_sums[i] = 0.0;
}

__global__ void k_count(const int* __restrict__ h, int E) {
    int e = blockIdx.x * blockDim.x + threadIdx.x;
    if (e < E) atomicAdd(&d_cnt[h[e]], 1);
}

__global__ void kA_bsum() {
    __shared__ int sw[8];
    int tid = threadIdx.x;
    int idx = blockIdx.x * 256 + tid;
    int c = (idx < NN) ? d_cnt[idx] : 0;
    int v = c;
    #pragma unroll
    for (int o = 16; o; o >>= 1) v += __shfl_xor_sync(0xffffffffu, v, o);
    if ((tid & 31) == 0) sw[tid >> 5] = v;
    __syncthreads();
    if (tid == 0) {
        int s = 0;
        #pragma unroll
        for (int i = 0; i < 8; i++) s += sw[i];
        d_bsum[blockIdx.x] = s;
    }
}

__global__ void kB_scan(int E) {
    __shared__ int ss[1024];
    int tid = threadIdx.x;
    int v = (tid < NBLK) ? d_bsum[tid] : 0;
    ss[tid] = v;
    __syncthreads();
    for (int o = 1; o < 1024; o <<= 1) {
        int x = ss[tid];
        if (tid >= o) x += ss[tid - o];
        __syncthreads();
        ss[tid] = x;
        __syncthreads();
    }
    if (tid < NBLK) d_bsum[tid] = ss[tid] - v;   // exclusive
    if (tid == 0) d_rowptr[NN] = E;
}

__global__ void kC_fill() {
    __shared__ int sh[256];
    int tid = threadIdx.x;
    int idx = blockIdx.x * 256 + tid;
    int c = (idx < NN) ? d_cnt[idx] : 0;
    sh[tid] = c;
    __syncthreads();
    for (int o = 1; o < 256; o <<= 1) {
        int x = sh[tid];
        if (tid >= o) x += sh[tid - o];
        __syncthreads();
        sh[tid] = x;
        __syncthreads();
    }
    if (idx < NN) {
        int p = d_bsum[blockIdx.x] + sh[tid] - c;
        d_rowptr[idx] = p;
        d_cnt[idx] = p;
        d_deg[idx] = rsqrtf((float)c);
    }
}

__global__ void k_bin(const int* __restrict__ h, const int* __restrict__ t, int E) {
    int e = blockIdx.x * blockDim.x + threadIdx.x;
    if (e >= E) return;
    int n = h[e], tt = t[e];
    int p = atomicAdd(&d_cnt[n], 1);
    d_epack[p] = make_int2(tt, __float_as_int(d_deg[n] * d_deg[tt]));
}

// ---------------- pull gather: 16 lanes per node ---------------------------
// pass 0: src = inputs, dst = cur, acc = ego + v
// pass 1: src = cur, dst = nxt, acc += v
// pass 2: src = nxt, no dst,    acc += v
__global__ void k_gather(const float4* __restrict__ ue, const float4* __restrict__ ie, int pass) {
    int gid = blockIdx.x * blockDim.x + threadIdx.x;
    int node = gid >> 4;
    if (node >= NN) return;
    int lane = gid & 15;
    int beg = __ldg(&d_rowptr[node]);
    int end = __ldg(&d_rowptr[node + 1]);
    float4 v = make_float4(0.f, 0.f, 0.f, 0.f);

    if (pass == 0) {
        int e = beg;
        for (; e + 1 < end; e += 2) {
            int2 p0 = __ldg(&d_epack[e]);
            int2 p1 = __ldg(&d_epack[e + 1]);
            const float4* s0 = (p0.x < NU) ? (ue + (size_t)p0.x * 16) : (ie + (size_t)(p0.x - NU) * 16);
            const float4* s1 = (p1.x < NU) ? (ue + (size_t)p1.x * 16) : (ie + (size_t)(p1.x - NU) * 16);
            float4 x0 = __ldg(s0 + lane);
            float4 x1 = __ldg(s1 + lane);
            float g0 = __int_as_float(p0.y), g1 = __int_as_float(p1.y);
            v.x += g0 * x0.x + g1 * x1.x;
            v.y += g0 * x0.y + g1 * x1.y;
            v.z += g0 * x0.z + g1 * x1.z;
            v.w += g0 * x0.w + g1 * x1.w;
        }
        if (e < end) {
            int2 p = __ldg(&d_epack[e]);
            const float4* s = (p.x < NU) ? (ue + (size_t)p.x * 16) : (ie + (size_t)(p.x - NU) * 16);
            float4 x = __ldg(s + lane);
            float g = __int_as_float(p.y);
            v.x += g * x.x; v.y += g * x.y; v.z += g * x.z; v.w += g * x.w;
        }
        size_t o = (size_t)node * 16 + lane;
        ((float4*)d_cur)[o] = v;
        const float4* ego = (node < NU) ? (ue + (size_t)node * 16) : (ie + (size_t)(node - NU) * 16);
        float4 e0 = __ldg(ego + lane);
        ((float4*)d_acc)[o] = make_float4(e0.x + v.x, e0.y + v.y, e0.z + v.z, e0.w + v.w);
    } else {
        const float4* __restrict__ src = (pass == 1) ? (const float4*)d_cur : (const float4*)d_nxt;
        int e = beg;
        for (; e + 1 < end; e += 2) {
            int2 p0 = __ldg(&d_epack[e]);
            int2 p1 = __ldg(&d_epack[e + 1]);
            float4 x0 = __ldg(src + (size_t)p0.x * 16 + lane);
            float4 x1 = __ldg(src + (size_t)p1.x * 16 + lane);
            float g0 = __int_as_float(p0.y), g1 = __int_as_float(p1.y);
            v.x += g0 * x0.x + g1 * x1.x;
            v.y += g0 * x0.y + g1 * x1.y;
            v.z += g0 * x0.z + g1 * x1.z;
            v.w += g0 * x0.w + g1 * x1.w;
        }
        if (e < end) {
            int2 p = __ldg(&d_epack[e]);
            float4 x = __ldg(src + (size_t)p.x * 16 + lane);
            float g = __int_as_float(p.y);
            v.x += g * x.x; v.y += g * x.y; v.z += g * x.z; v.w += g * x.w;
        }
        size_t o = (size_t)node * 16 + lane;
        if (pass == 1) ((float4*)d_nxt)[o] = v;
        float4 a = ((float4*)d_acc)[o];
        ((float4*)d_acc)[o] = make_float4(a.x + v.x, a.y + v.y, a.z + v.z, a.w + v.w);
    }
}

// ---------------- KL over all rows -----------------------------------------
__global__ void k_kl(const float* __restrict__ lin_w, const float* __restrict__ lin_b) {
    __shared__ float Wt[32 * 64];
    __shared__ float Bsh[64];
    __shared__ float warpsum[8];
    int tid = threadIdx.x;
    for (int i = tid; i < 2048; i += 256) {
        int d = i >> 5, tt = i & 31;
        Wt[tt * 64 + d] = lin_w[i];
    }
    if (tid < 64) Bsh[tid] = lin_b[tid];
    __syncthreads();
    int w = tid >> 5, lane = tid & 31;
    float local = 0.f;
    for (int it = 0; it < 4; it++) {
        int row = blockIdx.x * 32 + w * 4 + it;
        if (row < NN) {
            float a0 = d_acc[row * 64 + lane];
            float a1 = d_acc[row * 64 + 32 + lane];
            float sp = softplus_f(a0);
            float s0 = 0.f, s1 = 0.f;
            #pragma unroll
            for (int tt = 0; tt < 32; tt++) {
                float spt = __shfl_sync(0xffffffffu, sp, tt);
                s0 += spt * Wt[tt * 64 + lane];
                s1 += spt * Wt[tt * 64 + 32 + lane];
            }
            s0 += Bsh[lane] + 1e-8f;
            s1 += Bsh[lane + 32] + 1e-8f;
            float k0 = -0.5f * (1.f + 2.f * s0 - a0 * a0 - expf(2.f * s0));
            float k1 = -0.5f * (1.f + 2.f * s1 - a1 * a1 - expf(2.f * s1));
            if (!isfinite(k0)) k0 = 0.f;
            if (!isfinite(k1)) k1 = 0.f;
            local += k0 + k1;
        }
    }
    #pragma unroll
    for (int o = 16; o; o >>= 1) local += __shfl_xor_sync(0xffffffffu, local, o);
    if (lane == 0) warpsum[w] = local;
    __syncthreads();
    if (tid == 0) {
        float s = 0.f;
        for (int i = 0; i < 8; i++) s += warpsum[i];
        atomicAdd(&d_sums[0], (double)s);
    }
}

__global__ void k_bpr_emb(const float* __restrict__ ue, const float* __restrict__ ie,
                          const int* __restrict__ users, const int* __restrict__ pos,
                          const int* __restrict__ neg) {
    __shared__ float sb[8], se[8];
    int w = threadIdx.x >> 5, lane = threadIdx.x & 31;
    int b = blockIdx.x * 8 + w;
    float bpr = 0.f, emb = 0.f;
    {
        int u = users[b], pi = pos[b], ni = neg[b];
        float u0 = d_acc[u * 64 + lane],         u1 = d_acc[u * 64 + 32 + lane];
        float p0 = d_acc[(NU + pi) * 64 + lane], p1 = d_acc[(NU + pi) * 64 + 32 + lane];
        float n0 = d_acc[(NU + ni) * 64 + lane], n1 = d_acc[(NU + ni) * 64 + 32 + lane];
        float dsc = (u0 * n0 + u1 * n1) - (u0 * p0 + u1 * p1);
        float r0 = ue[u * 64 + lane],  r1 = ue[u * 64 + 32 + lane];
        float q0 = ie[pi * 64 + lane], q1 = ie[pi * 64 + 32 + lane];
        float m0 = ie[ni * 64 + lane], m1 = ie[ni * 64 + 32 + lane];
        float sq = r0 * r0 + r1 * r1 + q0 * q0 + q1 * q1 + m0 * m0 + m1 * m1;
        #pragma unroll
        for (int o = 16; o; o >>= 1) {
            dsc += __shfl_xor_sync(0xffffffffu, dsc, o);
            sq  += __shfl_xor_sync(0xffffffffu, sq, o);
        }
        if (lane == 0) { bpr = softplus_f(dsc); emb = sq; }
    }
    if (lane == 0) { sb[w] = bpr; se[w] = emb; }
    __syncthreads();
    if (threadIdx.x == 0) {
        float s1 = 0.f, s2 = 0.f;
        for (int i = 0; i < 8; i++) { s1 += sb[i]; s2 += se[i]; }
        atomicAdd(&d_sums[1], (double)s1);
        atomicAdd(&d_sums[2], (double)s2);
    }
}

// ---------------- build normalized CL rows (16 samples / block) ------------
__global__ void k_build_cl(const float* __restrict__ u_int_w, const float* __restrict__ i_int_w,
                           const float* __restrict__ lin_w, const float* __restrict__ lin_b,
                           const float* __restrict__ eps,
                           const int* __restrict__ users, const int* __restrict__ pos) {
    __shared__ float sI[64 * 129];
    __shared__ float sA[64];
    __shared__ float sSp[32];
    __shared__ float sP[128];
    __shared__ float sRed[128];
    __shared__ float sG[64], sO[64];
    int tid = threadIdx.x;
    int s = blockIdx.y;
    const float* intent = s ? i_int_w : u_int_w;

    for (int i = tid; i < 8192; i += 128)
        sI[(i >> 7) * 129 + (i & 127)] = intent[i];

    for (int bi = 0; bi < 16; bi++) {
        int b = blockIdx.x * 16 + bi;
        int r = s ? (NU + pos[b]) : users[b];
        if (tid < 64) sA[tid] = d_acc[r * 64 + tid];
        __syncthreads();
        if (tid < 32) sSp[tid] = softplus_f(sA[tid]);

        float lg = 0.f;
        #pragma unroll 8
        for (int d = 0; d < 64; d++) lg += sA[d] * sI[d * 129 + tid];

        sRed[tid] = lg; __syncthreads();
        for (int o = 64; o; o >>= 1) { if (tid < o) sRed[tid] = fmaxf(sRed[tid], sRed[tid + o]); __syncthreads(); }
        float mx = sRed[0]; __syncthreads();
        float pe = expf(lg - mx);
        sRed[tid] = pe; __syncthreads();
        for (int o = 64; o; o >>= 1) { if (tid < o) sRed[tid] += sRed[tid + o]; __syncthreads(); }
        float psum = sRed[0];
        sP[tid] = pe / psum;
        __syncthreads();

        float genv = 0.f, ov = 0.f;
        if (tid < 64) {
            #pragma unroll 8
            for (int k = 0; k < 128; k++) ov += sP[k] * sI[tid * 129 + k];
            float sd = 1e-8f + lin_b[tid];
            #pragma unroll
            for (int tt = 0; tt < 32; tt++) sd += sSp[tt] * lin_w[tid * 32 + tt];
            genv = sA[tid] + eps[r * 64 + tid] * sd;
            sG[tid] = genv * genv;
            sO[tid] = ov * ov;
        }
        __syncthreads();
        for (int o = 32; o; o >>= 1) { if (tid < o) { sG[tid] += sG[tid + o]; sO[tid] += sO[tid + o]; } __syncthreads(); }
        float gn = rsqrtf(sG[0]), on = rsqrtf(sO[0]);
        if (tid < 64) {
            float gnv = genv * gn, onv = ov * on;
            d_genN[(s * BB + b) * 64 + tid] = gnv;
            d_intN[(s * BB + b) * 64 + tid] = onv;
            sRed[tid] = gnv * onv;
        } else sRed[tid] = 0.f;
        __syncthreads();
        for (int o = 64; o; o >>= 1) { if (tid < o) sRed[tid] += sRed[tid + o]; __syncthreads(); }
        if (tid == 0) d_posS[s * BB + b] = sRed[0];
        __syncthreads();
    }
}

// ---------------- InfoNCE: packed f32x2 GEMM-like --------------------------
// grid (64 rowtiles, NCG=2 colgroups, 2 sides), 256 threads (16x16), 4x8/thread.
// k chunked by 32; duplicated-A and k-major B tiles with XOR swizzle.
#define NCG 2
__global__ __launch_bounds__(256, 2) void k_infonce() {
    __shared__ __align__(16) float As2[32][132];   // [k][dup cols 0..127 + pad]
    __shared__ __align__(16) float Bs[32][132];
    __shared__ float Rd[64][17];
    int s = blockIdx.z;
    int r0 = blockIdx.x * 64;
    int cg = blockIdx.y;
    const float* __restrict__ A  = d_genN + (size_t)s * BB * 64;
    const float* __restrict__ Bm = d_intN + (size_t)s * BB * 64;
    int tid = threadIdx.x;
    int tx = tid & 15, ty = tid >> 4;

    float rowAcc[4] = {0.f, 0.f, 0.f, 0.f};

    for (int ct = 0; ct < 2048 / 128; ct++) {
        int c0 = cg * 2048 + ct * 128;
        unsigned long long am[4][4];
        #pragma unroll
        for (int i = 0; i < 4; i++)
            #pragma unroll
            for (int j = 0; j < 4; j++) am[i][j] = 0ull;

        for (int kc = 0; kc < 64; kc += 32) {
            __syncthreads();
            // A chunk: 64 rows x 32 k, duplicated, swizzled
            for (int i = tid; i < 2048; i += 256) {
                int k = i & 31, r = i >> 5;
                float v = A[(size_t)(r0 + r) * 64 + kc + k];
                int col = (2 * r) ^ (((k >> 3) & 3) << 2);
                As2[k][col] = v;
                As2[k][col + 1] = v;
            }
            // B chunk: 128 cols x 32 k, swizzled
            for (int i = tid; i < 4096; i += 256) {
                int k = i & 31, c = i >> 5;
                float v = Bm[(size_t)(c0 + c) * 64 + kc + k];
                Bs[k][c ^ (((k >> 3) & 3) << 2)] = v;
            }
            __syncthreads();
            #pragma unroll
            for (int k = 0; k < 32; k++) {
                int sw = ((k >> 3) & 3) << 2;
                ulonglong2 aa = *(const ulonglong2*)&As2[k][(8 * ty) ^ sw];
                ulonglong2 ab = *(const ulonglong2*)&As2[k][(8 * ty + 4) ^ sw];
                ulonglong2 b0 = *(const ulonglong2*)&Bs[k][(8 * tx) ^ sw];
                ulonglong2 b1 = *(const ulonglong2*)&Bs[k][(8 * tx + 4) ^ sw];
                FFMA2(am[0][0], aa.x, b0.x); FFMA2(am[0][1], aa.x, b0.y);
                FFMA2(am[0][2], aa.x, b1.x); FFMA2(am[0][3], aa.x, b1.y);
                FFMA2(am[1][0], aa.y, b0.x); FFMA2(am[1][1], aa.y, b0.y);
                FFMA2(am[1][2], aa.y, b1.x); FFMA2(am[1][3], aa.y, b1.y);
                FFMA2(am[2][0], ab.x, b0.x); FFMA2(am[2][1], ab.x, b0.y);
                FFMA2(am[2][2], ab.x, b1.x); FFMA2(am[2][3], ab.x, b1.y);
                FFMA2(am[3][0], ab.y, b0.x); FFMA2(am[3][1], ab.y, b0.y);
                FFMA2(am[3][2], ab.y, b1.x); FFMA2(am[3][3], ab.y, b1.y);
            }
        }
        #pragma unroll
        for (int i = 0; i < 4; i++) {
            float t2 = 0.f;
            #pragma unroll
            for (int j = 0; j < 4; j++) {
                float lo, hi;
                UNPACK2(lo, hi, am[i][j]);
                t2 += __expf(lo * 5.0f) + __expf(hi * 5.0f);
            }
            rowAcc[i] += t2;
        }
    }
    __syncthreads();
    #pragma unroll
    for (int i = 0; i < 4; i++) Rd[ty * 4 + i][tx] = rowAcc[i];
    __syncthreads();
    if (tid < 64) {
        float sm = 0.f;
        #pragma unroll
        for (int x = 0; x < 16; x++) sm += Rd[tid][x];
        atomicAdd(&d_negS[s * BB + r0 + tid], sm);
    }
}

__global__ void k_final(const float* __restrict__ ui, const float* __restrict__ ii,
                        float* __restrict__ out) {
    __shared__ double sh[256];
    __shared__ double sh2[256];
    int tid = threadIdx.x;
    double isum = 0.0, clsum = 0.0;
    for (int i = tid; i < 8192; i += 256) {
        float a = ui[i], b2 = ii[i];
        isum += (double)a * a + (double)b2 * b2;
    }
    for (int i = tid; i < 2 * BB; i += 256) {
        float ng = d_negS[i];
        float p  = expf(d_posS[i] * 5.0f);
        clsum += -(double)logf(p / (ng + 1e-8f) + 1e-8f);
    }
    sh[tid] = isum; sh2[tid] = clsum;
    __syncthreads();
    for (int o = 128; o; o >>= 1) {
        if (tid < o) { sh[tid] += sh[tid + o]; sh2[tid] += sh2[tid + o]; }
        __syncthreads();
    }
    if (tid == 0) {
        double kl = d_sums[0], bpr = d_sums[1], emb = d_sums[2];
        out[0] = (float)(bpr / 4096.0 + 0.01 * (kl / 150000.0));
        out[1] = (float)(0.1 * (sh2[0] / 4096.0));
        out[2] = (float)(1e-5 * emb);
        out[3] = (float)(1e-5 * sh[0]);
    }
}

// ---------------- launch ---------------------------------------------------
extern "C" void kernel_launch(void* const* d_in, const int* in_sizes, int n_in,
                              void* d_out, int out_size) {
    (void)n_in; (void)out_size;
    const float* user_emb = (const float*)d_in[0];
    const float* item_emb = (const float*)d_in[1];
    const float* user_int = (const float*)d_in[2];
    const float* item_int = (const float*)d_in[3];
    const float* lin_w    = (const float*)d_in[4];
    const float* lin_b    = (const float*)d_in[5];
    const float* eps      = (const float*)d_in[6];
    const int*   h        = (const int*)d_in[7];
    const int*   t        = (const int*)d_in[8];
    const int*   users    = (const int*)d_in[9];
    const int*   pos      = (const int*)d_in[10];
    const int*   neg      = (const int*)d_in[11];
    int E = in_sizes[7];
    float* out = (float*)d_out;

    k_init<<<(NN + 255) / 256, 256>>>();
    k_count<<<(E + 255) / 256, 256>>>(h, E);
    kA_bsum<<<NBLK, 256>>>();
    kB_scan<<<1, 1024>>>(E);
    kC_fill<<<NBLK, 256>>>();
    k_bin<<<(E + 255) / 256, 256>>>(h, t, E);

    int gb = (NN * 16 + 255) / 256;
    k_gather<<<gb, 256>>>((const float4*)user_emb, (const float4*)item_emb, 0);
    k_gather<<<gb, 256>>>((const float4*)user_emb, (const float4*)item_emb, 1);
    k_gather<<<gb, 256>>>((const float4*)user_emb, (const float4*)item_emb, 2);

    k_kl<<<(NN + 31) / 32, 256>>>(lin_w, lin_b);
    k_bpr_emb<<<BB / 8, 256>>>(user_emb, item_emb, users, pos, neg);
    k_build_cl<<<dim3(BB / 16, 2), 128>>>(user_int, item_int, lin_w, lin_b, eps, users, pos);
    k_infonce<<<dim3(64, NCG, 2), 256>>>();
    k_final<<<1, 256>>>(user_int, item_int, out);
}

// round 5
// speedup vs baseline: 1.8020x; 1.2261x over previous
#include <cuda_runtime.h>
#include <cuda_fp16.h>
#include <cuda_bf16.h>
#include <math.h>

#define NU 50000
#define NI 100000
#define NN 150000
#define DD 64
#define BB 4096
#define EMAX 3150000
#define NBLK 586            // ceil(NN/256)

// ---------------- device scratch -------------------------------------------
__device__ float  d_deg[NN];            // dinv = deg^-0.5
__device__ float  d_rdeg[NN];           // sqrt(deg)
__device__ int    d_cnt[NN];            // counts, then bin cursors
__device__ int    d_bsum[1024];
__device__ int    d_rowptr[NN + 1];
__device__ int    d_et[EMAX];           // CSR-sorted target ids
__device__ __half d_egoh[NN * DD];      // s0 = dinv * ego
__device__ __half d_curh[NN * DD];      // s1
__device__ __half d_nxth[NN * DD];      // s2
__device__ float  d_acc[NN * DD];
__device__ float  d_genN[2 * BB * DD];
__device__ float  d_intN[2 * BB * DD];
__device__ float  d_negS[2 * BB];
__device__ float  d_posS[2 * BB];
__device__ double d_sums[4];            // 0: kl, 1: bpr, 2: emb

__device__ __forceinline__ float softplus_f(float x) {
    return x > 0.f ? x + log1pf(expf(-x)) : log1pf(expf(x));
}

#define FFMA2(d, a, b) asm("fma.rn.f32x2 %0, %1, %2, %0;" : "+l"(d) : "l"(a), "l"(b))
#define UNPACK2(lo, hi, v) asm("mov.b64 {%0,%1}, %2;" : "=f"(lo), "=f"(hi) : "l"(v))

// ---------------- CSR build ------------------------------------------------
__global__ void k_init() {
    int i = blockIdx.x * blockDim.x + threadIdx.x;
    if (i < NN) d_cnt[i] = 0;
    if (i < 2 * BB) d_negS[i] = 0.f;
    if (i < 4) d_sums[i] = 0.0;
}

__global__ void k_count(const int* __restrict__ h, int E) {
    int e = blockIdx.x * blockDim.x + threadIdx.x;
    if (e < E) atomicAdd(&d_cnt[h[e]], 1);
}

__global__ void kA_bsum() {
    __shared__ int sw[8];
    int tid = threadIdx.x;
    int idx = blockIdx.x * 256 + tid;
    int c = (idx < NN) ? d_cnt[idx] : 0;
    int v = c;
    #pragma unroll
    for (int o = 16; o; o >>= 1) v += __shfl_xor_sync(0xffffffffu, v, o);
    if ((tid & 31) == 0) sw[tid >> 5] = v;
    __syncthreads();
    if (tid == 0) {
        int s = 0;
        #pragma unroll
        for (int i = 0; i < 8; i++) s += sw[i];
        d_bsum[blockIdx.x] = s;
    }
}

__global__ void kB_scan(int E) {
    __shared__ int ss[1024];
    int tid = threadIdx.x;
    int v = (tid < NBLK) ? d_bsum[tid] : 0;
    ss[tid] = v;
    __syncthreads();
    for (int o = 1; o < 1024; o <<= 1) {
        int x = ss[tid];
        if (tid >= o) x += ss[tid - o];
        __syncthreads();
        ss[tid] = x;
        __syncthreads();
    }
    if (tid < NBLK) d_bsum[tid] = ss[tid] - v;
    if (tid == 0) d_rowptr[NN] = E;
}

__global__ void kC_fill() {
    __shared__ int sh[256];
    int tid = threadIdx.x;
    int idx = blockIdx.x * 256 + tid;
    int c = (idx < NN) ? d_cnt[idx] : 0;
    sh[tid] = c;
    __syncthreads();
    for (int o = 1; o < 256; o <<= 1) {
        int x = sh[tid];
        if (tid >= o) x += sh[tid - o];
        __syncthreads();
        sh[tid] = x;
        __syncthreads();
    }
    if (idx < NN) {
        int p = d_bsum[blockIdx.x] + sh[tid] - c;
        d_rowptr[idx] = p;
        d_cnt[idx] = p;
        float fc = (float)c;
        d_deg[idx] = rsqrtf(fc);
        d_rdeg[idx] = sqrtf(fc);
    }
}

__global__ void k_bin(const int* __restrict__ h, const int* __restrict__ t, int E) {
    int e = blockIdx.x * blockDim.x + threadIdx.x;
    if (e >= E) return;
    int n = h[e];
    int p = atomicAdd(&d_cnt[n], 1);
    d_et[p] = t[e];
}

// egoh = half(dinv[node] * ego)
__global__ void k_tohalf(const float4* __restrict__ ue, const float4* __restrict__ ie) {
    int i = blockIdx.x * blockDim.x + threadIdx.x;
    if (i >= NN * 16) return;
    int node = i >> 4;
    float4 v = (node < NU) ? __ldg(ue + i) : __ldg(ie + (i - NU * 16));
    float s = d_deg[node];
    union { uint2 u; __half2 h[2]; } o;
    o.h[0] = __floats2half2_rn(s * v.x, s * v.y);
    o.h[1] = __floats2half2_rn(s * v.z, s * v.w);
    ((uint2*)d_egoh)[i] = o.u;
}

// ---------------- pull gather: 8 lanes per node, half rows -----------------
__device__ __forceinline__ void add8(float* v, uint4 x) {
    union { uint4 u; __half2 h[4]; } c; c.u = x;
    float2 f;
    f = __half22float2(c.h[0]); v[0] += f.x; v[1] += f.y;
    f = __half22float2(c.h[1]); v[2] += f.x; v[3] += f.y;
    f = __half22float2(c.h[2]); v[4] += f.x; v[5] += f.y;
    f = __half22float2(c.h[3]); v[6] += f.x; v[7] += f.y;
}

__global__ void k_gather(const float4* __restrict__ ue, const float4* __restrict__ ie, int pass) {
    int gid = blockIdx.x * blockDim.x + threadIdx.x;
    int node = gid >> 3;
    if (node >= NN) return;
    int lane = gid & 7;
    int beg = __ldg(&d_rowptr[node]);
    int end = __ldg(&d_rowptr[node + 1]);
    const uint4* __restrict__ src =
        (pass == 0) ? (const uint4*)d_egoh :
        (pass == 1) ? (const uint4*)d_curh : (const uint4*)d_nxth;
    float v[8] = {0.f, 0.f, 0.f, 0.f, 0.f, 0.f, 0.f, 0.f};
    int e = beg;
    for (; e + 1 < end; e += 2) {
        int t0 = __ldg(&d_et[e]);
        int t1 = __ldg(&d_et[e + 1]);
        uint4 x0 = __ldg(src + (size_t)t0 * 8 + lane);
        uint4 x1 = __ldg(src + (size_t)t1 * 8 + lane);
        add8(v, x0);
        add8(v, x1);
    }
    if (e < end) {
        int t0 = __ldg(&d_et[e]);
        add8(v, __ldg(src + (size_t)t0 * 8 + lane));
    }
    float dinv = __ldg(&d_deg[node]);
    if (pass < 2) {
        float s = dinv * dinv;             // store s_{k+1} = dinv^2 * g
        union { uint4 u; __half2 h[4]; } o;
        o.h[0] = __floats2half2_rn(s * v[0], s * v[1]);
        o.h[1] = __floats2half2_rn(s * v[2], s * v[3]);
        o.h[2] = __floats2half2_rn(s * v[4], s * v[5]);
        o.h[3] = __floats2half2_rn(s * v[6], s * v[7]);
        uint4* dst = (pass == 0) ? (uint4*)d_curh : (uint4*)d_nxth;
        dst[(size_t)node * 8 + lane] = o.u;
    } else {
        float rd = __ldg(&d_rdeg[node]);
        union { uint4 u; __half2 h[4]; } a, b;
        a.u = __ldg((const uint4*)d_curh + (size_t)node * 8 + lane);
        b.u = __ldg((const uint4*)d_nxth + (size_t)node * 8 + lane);
        const float4* ego = (node < NU) ? (ue + (size_t)node * 16)
                                        : (ie + (size_t)(node - NU) * 16);
        float4 e0 = __ldg(ego + lane * 2);
        float4 e1 = __ldg(ego + lane * 2 + 1);
        float s12[8];
        {
            float2 f0 = __half22float2(a.h[0]), g0 = __half22float2(b.h[0]);
            float2 f1 = __half22float2(a.h[1]), g1 = __half22float2(b.h[1]);
            float2 f2 = __half22float2(a.h[2]), g2 = __half22float2(b.h[2]);
            float2 f3 = __half22float2(a.h[3]), g3 = __half22float2(b.h[3]);
            s12[0] = f0.x + g0.x; s12[1] = f0.y + g0.y;
            s12[2] = f1.x + g1.x; s12[3] = f1.y + g1.y;
            s12[4] = f2.x + g2.x; s12[5] = f2.y + g2.y;
            s12[6] = f3.x + g3.x; s12[7] = f3.y + g3.y;
        }
        float4 o0, o1;
        o0.x = e0.x + rd * s12[0] + dinv * v[0];
        o0.y = e0.y + rd * s12[1] + dinv * v[1];
        o0.z = e0.z + rd * s12[2] + dinv * v[2];
        o0.w = e0.w + rd * s12[3] + dinv * v[3];
        o1.x = e1.x + rd * s12[4] + dinv * v[4];
        o1.y = e1.y + rd * s12[5] + dinv * v[5];
        o1.z = e1.z + rd * s12[6] + dinv * v[6];
        o1.w = e1.w + rd * s12[7] + dinv * v[7];
        float4* ap = (float4*)(d_acc + (size_t)node * 64 + lane * 8);
        __stcs(ap, o0);
        __stcs(ap + 1, o1);
    }
}

// ---------------- KL over all rows -----------------------------------------
__global__ void k_kl(const float* __restrict__ lin_w, const float* __restrict__ lin_b) {
    __shared__ float Wt[32 * 64];
    __shared__ float Bsh[64];
    __shared__ float warpsum[8];
    int tid = threadIdx.x;
    for (int i = tid; i < 2048; i += 256) {
        int d = i >> 5, tt = i & 31;
        Wt[tt * 64 + d] = lin_w[i];
    }
    if (tid < 64) Bsh[tid] = lin_b[tid];
    __syncthreads();
    int w = tid >> 5, lane = tid & 31;
    float local = 0.f;
    for (int it = 0; it < 4; it++) {
        int row = blockIdx.x * 32 + w * 4 + it;
        if (row < NN) {
            float a0 = d_acc[row * 64 + lane];
            float a1 = d_acc[row * 64 + 32 + lane];
            float sp = softplus_f(a0);
            float s0 = 0.f, s1 = 0.f;
            #pragma unroll
            for (int tt = 0; tt < 32; tt++) {
                float spt = __shfl_sync(0xffffffffu, sp, tt);
                s0 += spt * Wt[tt * 64 + lane];
                s1 += spt * Wt[tt * 64 + 32 + lane];
            }
            s0 += Bsh[lane] + 1e-8f;
            s1 += Bsh[lane + 32] + 1e-8f;
            float k0 = -0.5f * (1.f + 2.f * s0 - a0 * a0 - expf(2.f * s0));
            float k1 = -0.5f * (1.f + 2.f * s1 - a1 * a1 - expf(2.f * s1));
            if (!isfinite(k0)) k0 = 0.f;
            if (!isfinite(k1)) k1 = 0.f;
            local += k0 + k1;
        }
    }
    #pragma unroll
    for (int o = 16; o; o >>= 1) local += __shfl_xor_sync(0xffffffffu, local, o);
    if (lane == 0) warpsum[w] = local;
    __syncthreads();
    if (tid == 0) {
        float s = 0.f;
        for (int i = 0; i < 8; i++) s += warpsum[i];
        atomicAdd(&d_sums[0], (double)s);
    }
}

__global__ void k_bpr_emb(const float* __restrict__ ue, const float* __restrict__ ie,
                          const int* __restrict__ users, const int* __restrict__ pos,
                          const int* __restrict__ neg) {
    __shared__ float sb[8], se[8];
    int w = threadIdx.x >> 5, lane = threadIdx.x & 31;
    int b = blockIdx.x * 8 + w;
    float bpr = 0.f, emb = 0.f;
    {
        int u = users[b], pi = pos[b], ni = neg[b];
        float u0 = d_acc[u * 64 + lane],         u1 = d_acc[u * 64 + 32 + lane];
        float p0 = d_acc[(NU + pi) * 64 + lane], p1 = d_acc[(NU + pi) * 64 + 32 + lane];
        float n0 = d_acc[(NU + ni) * 64 + lane], n1 = d_acc[(NU + ni) * 64 + 32 + lane];
        float dsc = (u0 * n0 + u1 * n1) - (u0 * p0 + u1 * p1);
        float r0 = ue[u * 64 + lane],  r1 = ue[u * 64 + 32 + lane];
        float q0 = ie[pi * 64 + lane], q1 = ie[pi * 64 + 32 + lane];
        float m0 = ie[ni * 64 + lane], m1 = ie[ni * 64 + 32 + lane];
        float sq = r0 * r0 + r1 * r1 + q0 * q0 + q1 * q1 + m0 * m0 + m1 * m1;
        #pragma unroll
        for (int o = 16; o; o >>= 1) {
            dsc += __shfl_xor_sync(0xffffffffu, dsc, o);
            sq  += __shfl_xor_sync(0xffffffffu, sq, o);
        }
        if (lane == 0) { bpr = softplus_f(dsc); emb = sq; }
    }
    if (lane == 0) { sb[w] = bpr; se[w] = emb; }
    __syncthreads();
    if (threadIdx.x == 0) {
        float s1 = 0.f, s2 = 0.f;
        for (int i = 0; i < 8; i++) { s1 += sb[i]; s2 += se[i]; }
        atomicAdd(&d_sums[1], (double)s1);
        atomicAdd(&d_sums[2], (double)s2);
    }
}

// ---------------- build normalized CL rows (16 samples / block) ------------
__global__ void k_build_cl(const float* __restrict__ u_int_w, const float* __restrict__ i_int_w,
                           const float* __restrict__ lin_w, const float* __restrict__ lin_b,
                           const float* __restrict__ eps,
                           const int* __restrict__ users, const int* __restrict__ pos) {
    __shared__ float sI[64 * 129];
    __shared__ float sA[64];
    __shared__ float sSp[32];
    __shared__ float sP[128];
    __shared__ float sRed[128];
    __shared__ float sG[64], sO[64];
    int tid = threadIdx.x;
    int s = blockIdx.y;
    const float* intent = s ? i_int_w : u_int_w;

    for (int i = tid; i < 8192; i += 128)
        sI[(i >> 7) * 129 + (i & 127)] = intent[i];

    for (int bi = 0; bi < 16; bi++) {
        int b = blockIdx.x * 16 + bi;
        int r = s ? (NU + pos[b]) : users[b];
        if (tid < 64) sA[tid] = d_acc[r * 64 + tid];
        __syncthreads();
        if (tid < 32) sSp[tid] = softplus_f(sA[tid]);

        float lg = 0.f;
        #pragma unroll 8
        for (int d = 0; d < 64; d++) lg += sA[d] * sI[d * 129 + tid];

        sRed[tid] = lg; __syncthreads();
        for (int o = 64; o; o >>= 1) { if (tid < o) sRed[tid] = fmaxf(sRed[tid], sRed[tid + o]); __syncthreads(); }
        float mx = sRed[0]; __syncthreads();
        float pe = expf(lg - mx);
        sRed[tid] = pe; __syncthreads();
        for (int o = 64; o; o >>= 1) { if (tid < o) sRed[tid] += sRed[tid + o]; __syncthreads(); }
        float psum = sRed[0];
        sP[tid] = pe / psum;
        __syncthreads();

        float genv = 0.f, ov = 0.f;
        if (tid < 64) {
            #pragma unroll 8
            for (int k = 0; k < 128; k++) ov += sP[k] * sI[tid * 129 + k];
            float sd = 1e-8f + lin_b[tid];
            #pragma unroll
            for (int tt = 0; tt < 32; tt++) sd += sSp[tt] * lin_w[tid * 32 + tt];
            genv = sA[tid] + eps[r * 64 + tid] * sd;
            sG[tid] = genv * genv;
            sO[tid] = ov * ov;
        }
        __syncthreads();
        for (int o = 32; o; o >>= 1) { if (tid < o) { sG[tid] += sG[tid + o]; sO[tid] += sO[tid + o]; } __syncthreads(); }
        float gn = rsqrtf(sG[0]), on = rsqrtf(sO[0]);
        if (tid < 64) {
            float gnv = genv * gn, onv = ov * on;
            d_genN[(s * BB + b) * 64 + tid] = gnv;
            d_intN[(s * BB + b) * 64 + tid] = onv;
            sRed[tid] = gnv * onv;
        } else sRed[tid] = 0.f;
        __syncthreads();
        for (int o = 64; o; o >>= 1) { if (tid < o) sRed[tid] += sRed[tid + o]; __syncthreads(); }
        if (tid == 0) d_posS[s * BB + b] = sRed[0];
        __syncthreads();
    }
}

// ---------------- InfoNCE: packed f32x2 GEMM-like --------------------------
#define NCG 2
__global__ __launch_bounds__(256, 2) void k_infonce() {
    __shared__ __align__(16) float As2[32][132];
    __shared__ __align__(16) float Bs[32][132];
    __shared__ float Rd[64][17];
    int s = blockIdx.z;
    int r0 = blockIdx.x * 64;
    int cg = blockIdx.y;
    const float* __restrict__ A  = d_genN + (size_t)s * BB * 64;
    const float* __restrict__ Bm = d_intN + (size_t)s * BB * 64;
    int tid = threadIdx.x;
    int tx = tid & 15, ty = tid >> 4;

    float rowAcc[4] = {0.f, 0.f, 0.f, 0.f};

    for (int ct = 0; ct < 2048 / 128; ct++) {
        int c0 = cg * 2048 + ct * 128;
        unsigned long long am[4][4];
        #pragma unroll
        for (int i = 0; i < 4; i++)
            #pragma unroll
            for (int j = 0; j < 4; j++) am[i][j] = 0ull;

        for (int kc = 0; kc < 64; kc += 32) {
            __syncthreads();
            for (int i = tid; i < 2048; i += 256) {
                int k = i & 31, r = i >> 5;
                float v = A[(size_t)(r0 + r) * 64 + kc + k];
                int col = (2 * r) ^ (((k >> 3) & 3) << 2);
                As2[k][col] = v;
                As2[k][col + 1] = v;
            }
            for (int i = tid; i < 4096; i += 256) {
                int k = i & 31, c = i >> 5;
                float v = Bm[(size_t)(c0 + c) * 64 + kc + k];
                Bs[k][c ^ (((k >> 3) & 3) << 2)] = v;
            }
            __syncthreads();
            #pragma unroll
            for (int k = 0; k < 32; k++) {
                int sw = ((k >> 3) & 3) << 2;
                ulonglong2 aa = *(const ulonglong2*)&As2[k][(8 * ty) ^ sw];
                ulonglong2 ab = *(const ulonglong2*)&As2[k][(8 * ty + 4) ^ sw];
                ulonglong2 b0 = *(const ulonglong2*)&Bs[k][(8 * tx) ^ sw];
                ulonglong2 b1 = *(const ulonglong2*)&Bs[k][(8 * tx + 4) ^ sw];
                FFMA2(am[0][0], aa.x, b0.x); FFMA2(am[0][1], aa.x, b0.y);
                FFMA2(am[0][2], aa.x, b1.x); FFMA2(am[0][3], aa.x, b1.y);
                FFMA2(am[1][0], aa.y, b0.x); FFMA2(am[1][1], aa.y, b0.y);
                FFMA2(am[1][2], aa.y, b1.x); FFMA2(am[1][3], aa.y, b1.y);
                FFMA2(am[2][0], ab.x, b0.x); FFMA2(am[2][1], ab.x, b0.y);
                FFMA2(am[2][2], ab.x, b1.x); FFMA2(am[2][3], ab.x, b1.y);
                FFMA2(am[3][0], ab.y, b0.x); FFMA2(am[3][1], ab.y, b0.y);
                FFMA2(am[3][2], ab.y, b1.x); FFMA2(am[3][3], ab.y, b1.y);
            }
        }
        #pragma unroll
        for (int i = 0; i < 4; i++) {
            float t2 = 0.f;
            #pragma unroll
            for (int j = 0; j < 4; j++) {
                float lo, hi;
                UNPACK2(lo, hi, am[i][j]);
                t2 += __expf(lo * 5.0f) + __expf(hi * 5.0f);
            }
            rowAcc[i] += t2;
        }
    }
    __syncthreads();
    #pragma unroll
    for (int i = 0; i < 4; i++) Rd[ty * 4 + i][tx] = rowAcc[i];
    __syncthreads();
    if (tid < 64) {
        float sm = 0.f;
        #pragma unroll
        for (int x = 0; x < 16; x++) sm += Rd[tid][x];
        atomicAdd(&d_negS[s * BB + r0 + tid], sm);
    }
}

__global__ void k_final(const float* __restrict__ ui, const float* __restrict__ ii,
                        float* __restrict__ out) {
    __shared__ double sh[256];
    __shared__ double sh2[256];
    int tid = threadIdx.x;
    double isum = 0.0, clsum = 0.0;
    for (int i = tid; i < 8192; i += 256) {
        float a = ui[i], b2 = ii[i];
        isum += (double)a * a + (double)b2 * b2;
    }
    for (int i = tid; i < 2 * BB; i += 256) {
        float ng = d_negS[i];
        float p  = expf(d_posS[i] * 5.0f);
        clsum += -(double)logf(p / (ng + 1e-8f) + 1e-8f);
    }
    sh[tid] = isum; sh2[tid] = clsum;
    __syncthreads();
    for (int o = 128; o; o >>= 1) {
        if (tid < o) { sh[tid] += sh[tid + o]; sh2[tid] += sh2[tid + o]; }
        __syncthreads();
    }
    if (tid == 0) {
        double kl = d_sums[0], bpr = d_sums[1], emb = d_sums[2];
        out[0] = (float)(bpr / 4096.0 + 0.01 * (kl / 150000.0));
        out[1] = (float)(0.1 * (sh2[0] / 4096.0));
        out[2] = (float)(1e-5 * emb);
        out[3] = (float)(1e-5 * sh[0]);
    }
}

// ---------------- launch ---------------------------------------------------
extern "C" void kernel_launch(void* const* d_in, const int* in_sizes, int n_in,
                              void* d_out, int out_size) {
    (void)n_in; (void)out_size;
    const float* user_emb = (const float*)d_in[0];
    const float* item_emb = (const float*)d_in[1];
    const float* user_int = (const float*)d_in[2];
    const float* item_int = (const float*)d_in[3];
    const float* lin_w    = (const float*)d_in[4];
    const float* lin_b    = (const float*)d_in[5];
    const float* eps      = (const float*)d_in[6];
    const int*   h        = (const int*)d_in[7];
    const int*   t        = (const int*)d_in[8];
    const int*   users    = (const int*)d_in[9];
    const int*   pos      = (const int*)d_in[10];
    const int*   neg      = (const int*)d_in[11];
    int E = in_sizes[7];
    float* out = (float*)d_out;

    k_init<<<(NN + 255) / 256, 256>>>();
    k_count<<<(E + 255) / 256, 256>>>(h, E);
    kA_bsum<<<NBLK, 256>>>();
    kB_scan<<<1, 1024>>>(E);
    kC_fill<<<NBLK, 256>>>();
    k_bin<<<(E + 255) / 256, 256>>>(h, t, E);
    k_tohalf<<<(NN * 16 + 255) / 256, 256>>>((const float4*)user_emb, (const float4*)item_emb);

    int gb = (NN * 8 + 255) / 256;
    k_gather<<<gb, 256>>>((const float4*)user_emb, (const float4*)item_emb, 0);
    k_gather<<<gb, 256>>>((const float4*)user_emb, (const float4*)item_emb, 1);
    k_gather<<<gb, 256>>>((const float4*)user_emb, (const float4*)item_emb, 2);

    k_kl<<<(NN + 31) / 32, 256>>>(lin_w, lin_b);
    k_bpr_emb<<<BB / 8, 256>>>(user_emb, item_emb, users, pos, neg);
    k_build_cl<<<dim3(BB / 16, 2), 128>>>(user_int, item_int, lin_w, lin_b, eps, users, pos);
    k_infonce<<<dim3(64, NCG, 2), 256>>>();
    k_final<<<1, 256>>>(user_int, item_int, out);
}

// round 8
// speedup vs baseline: 2.2026x; 1.2223x over previous
#include <cuda_runtime.h>
#include <cuda_fp16.h>
#include <cuda_bf16.h>
#include <math.h>

#define NU 50000
#define NI 100000
#define NN 150000
#define DD 64
#define BB 4096
#define EMAX 3150000
#define NBLK 586            // ceil(NN/256)

// ---------------- device scratch -------------------------------------------
__device__ float  d_deg[NN];            // dinv = deg^-0.5
__device__ float  d_rdeg[NN];           // sqrt(deg)
__device__ int    d_cnt[NN];            // counts -> cursors (reset by gather p0)
__device__ int    d_bsum[1024];
__device__ int    d_rowptr[NN + 1];
__device__ int    d_et[EMAX];           // CSR-sorted target ids
__device__ __half d_egoh[NN * DD];      // s0 = dinv * ego
__device__ __half d_curh[NN * DD];      // s1
__device__ __half d_nxth[NN * DD];      // s2
__device__ float  d_acc[NN * DD];
__device__ __half d_genH[2 * BB * DD];
__device__ __half d_intH[2 * BB * DD];
__device__ float  d_negS[2 * BB];       // zeroed by k_final after use
__device__ float  d_posS[2 * BB];
__device__ double d_sums[4];            // 0: kl, 1: bpr, 2: emb (zeroed by k_final)

__device__ __forceinline__ float softplus_f(float x) {
    return x > 0.f ? x + log1pf(expf(-x)) : log1pf(expf(x));
}

__device__ __forceinline__ unsigned smem_u32(const void* p) {
    return (unsigned)__cvta_generic_to_shared(p);
}

__device__ __forceinline__ void ldsm_x4(unsigned &r0, unsigned &r1, unsigned &r2, unsigned &r3, unsigned addr) {
    asm volatile("ldmatrix.sync.aligned.m8n8.x4.shared.b16 {%0,%1,%2,%3}, [%4];"
                 : "=r"(r0), "=r"(r1), "=r"(r2), "=r"(r3) : "r"(addr));
}
__device__ __forceinline__ void ldsm_x2(unsigned &r0, unsigned &r1, unsigned addr) {
    asm volatile("ldmatrix.sync.aligned.m8n8.x2.shared.b16 {%0,%1}, [%2];"
                 : "=r"(r0), "=r"(r1) : "r"(addr));
}
__device__ __forceinline__ void mma16816(float* c, unsigned a0, unsigned a1, unsigned a2, unsigned a3,
                                         unsigned b0, unsigned b1) {
    asm volatile("mma.sync.aligned.m16n8k16.row.col.f32.f16.f16.f32 "
                 "{%0,%1,%2,%3}, {%4,%5,%6,%7}, {%8,%9}, {%0,%1,%2,%3};"
                 : "+f"(c[0]), "+f"(c[1]), "+f"(c[2]), "+f"(c[3])
                 : "r"(a0), "r"(a1), "r"(a2), "r"(a3), "r"(b0), "r"(b1));
}

// ---------------- CSR build ------------------------------------------------
__global__ void k_count(const int* __restrict__ h, int E) {
    int e = blockIdx.x * blockDim.x + threadIdx.x;
    if (e < E) atomicAdd(&d_cnt[h[e]], 1);
}

__global__ void kA_bsum() {
    __shared__ int sw[8];
    int tid = threadIdx.x;
    int idx = blockIdx.x * 256 + tid;
    int c = (idx < NN) ? d_cnt[idx] : 0;
    int v = c;
    #pragma unroll
    for (int o = 16; o; o >>= 1) v += __shfl_xor_sync(0xffffffffu, v, o);
    if ((tid & 31) == 0) sw[tid >> 5] = v;
    __syncthreads();
    if (tid == 0) {
        int s = 0;
        #pragma unroll
        for (int i = 0; i < 8; i++) s += sw[i];
        d_bsum[blockIdx.x] = s;
    }
}

__global__ void kB_scan(int E) {
    __shared__ int ss[1024];
    int tid = threadIdx.x;
    int v = (tid < NBLK) ? d_bsum[tid] : 0;
    ss[tid] = v;
    __syncthreads();
    for (int o = 1; o < 1024; o <<= 1) {
        int x = ss[tid];
        if (tid >= o) x += ss[tid - o];
        __syncthreads();
        ss[tid] = x;
        __syncthreads();
    }
    if (tid < NBLK) d_bsum[tid] = ss[tid] - v;
    if (tid == 0) d_rowptr[NN] = E;
}

// scan within block -> rowptr/cursors/deg, then convert this block's ego rows to half
__global__ void kC_fill(const float4* __restrict__ ue, const float4* __restrict__ ie) {
    __shared__ int   sh[256];
    __shared__ float sdeg[256];
    int tid = threadIdx.x;
    int idx = blockIdx.x * 256 + tid;
    int c = (idx < NN) ? d_cnt[idx] : 0;
    sh[tid] = c;
    __syncthreads();
    for (int o = 1; o < 256; o <<= 1) {
        int x = sh[tid];
        if (tid >= o) x += sh[tid - o];
        __syncthreads();
        sh[tid] = x;
        __syncthreads();
    }
    float dinv = rsqrtf((float)c);
    if (idx < NN) {
        int p = d_bsum[blockIdx.x] + sh[tid] - c;
        d_rowptr[idx] = p;
        d_cnt[idx] = p;
        d_deg[idx] = dinv;
        d_rdeg[idx] = sqrtf((float)c);
    }
    sdeg[tid] = dinv;
    __syncthreads();
    int base_node = blockIdx.x * 256;
    for (int i = tid; i < 4096; i += 256) {
        int node = base_node + (i >> 4);
        if (node >= NN) continue;
        int ch = i & 15;
        float4 v = (node < NU) ? __ldg(ue + (size_t)node * 16 + ch)
                               : __ldg(ie + (size_t)(node - NU) * 16 + ch);
        float s = sdeg[i >> 4];
        union { uint2 u; __half2 h[2]; } o;
        o.h[0] = __floats2half2_rn(s * v.x, s * v.y);
        o.h[1] = __floats2half2_rn(s * v.z, s * v.w);
        ((uint2*)d_egoh)[(size_t)node * 16 + ch] = o.u;
    }
}

__global__ void k_bin(const int* __restrict__ h, const int* __restrict__ t, int E) {
    int e = blockIdx.x * blockDim.x + threadIdx.x;
    if (e >= E) return;
    int n = h[e];
    int p = atomicAdd(&d_cnt[n], 1);
    d_et[p] = t[e];
}

// ---------------- pull gather: one warp per node, 4 edges in flight --------
__device__ __forceinline__ void add8(float* v, uint4 x) {
    union { uint4 u; __half2 h[4]; } c; c.u = x;
    float2 f;
    f = __half22float2(c.h[0]); v[0] += f.x; v[1] += f.y;
    f = __half22float2(c.h[1]); v[2] += f.x; v[3] += f.y;
    f = __half22float2(c.h[2]); v[4] += f.x; v[5] += f.y;
    f = __half22float2(c.h[3]); v[6] += f.x; v[7] += f.y;
}

__global__ void k_gather(const float4* __restrict__ ue, const float4* __restrict__ ie, int pass) {
    int node = (blockIdx.x * blockDim.x + threadIdx.x) >> 5;
    if (node >= NN) return;
    int lane = threadIdx.x & 31;
    int sub = lane >> 3, ch = lane & 7;
    int beg = __ldg(&d_rowptr[node]);
    int end = __ldg(&d_rowptr[node + 1]);
    const uint4* __restrict__ src =
        (pass == 0) ? (const uint4*)d_egoh :
        (pass == 1) ? (const uint4*)d_curh : (const uint4*)d_nxth;
    float v[8] = {0.f, 0.f, 0.f, 0.f, 0.f, 0.f, 0.f, 0.f};
    int e = beg + sub;
    for (; e + 4 < end; e += 8) {
        int t0 = __ldg(&d_et[e]);
        int t1 = __ldg(&d_et[e + 4]);
        uint4 x0 = __ldg(src + (size_t)t0 * 8 + ch);
        uint4 x1 = __ldg(src + (size_t)t1 * 8 + ch);
        add8(v, x0);
        add8(v, x1);
    }
    if (e < end) {
        int t0 = __ldg(&d_et[e]);
        add8(v, __ldg(src + (size_t)t0 * 8 + ch));
    }
    // reduce across the 4 edge slots
    #pragma unroll
    for (int j = 0; j < 8; j++) {
        v[j] += __shfl_xor_sync(0xffffffffu, v[j], 8);
        v[j] += __shfl_xor_sync(0xffffffffu, v[j], 16);
    }
    float dinv = __ldg(&d_deg[node]);
    if (pass == 0 && lane == 0) d_cnt[node] = 0;  // recycle for next replay
    if (sub != 0) return;
    if (pass < 2) {
        float s = dinv * dinv;
        union { uint4 u; __half2 h[4]; } o;
        o.h[0] = __floats2half2_rn(s * v[0], s * v[1]);
        o.h[1] = __floats2half2_rn(s * v[2], s * v[3]);
        o.h[2] = __floats2half2_rn(s * v[4], s * v[5]);
        o.h[3] = __floats2half2_rn(s * v[6], s * v[7]);
        uint4* dst = (pass == 0) ? (uint4*)d_curh : (uint4*)d_nxth;
        dst[(size_t)node * 8 + ch] = o.u;
    } else {
        float rd = __ldg(&d_rdeg[node]);
        union { uint4 u; __half2 h[4]; } a, b;
        a.u = __ldg((const uint4*)d_curh + (size_t)node * 8 + ch);
        b.u = __ldg((const uint4*)d_nxth + (size_t)node * 8 + ch);
        const float4* ego = (node < NU) ? (ue + (size_t)node * 16)
                                        : (ie + (size_t)(node - NU) * 16);
        float4 e0 = __ldg(ego + ch * 2);
        float4 e1 = __ldg(ego + ch * 2 + 1);
        float s12[8];
        {
            float2 f0 = __half22float2(a.h[0]), g0 = __half22float2(b.h[0]);
            float2 f1 = __half22float2(a.h[1]), g1 = __half22float2(b.h[1]);
            float2 f2 = __half22float2(a.h[2]), g2 = __half22float2(b.h[2]);
            float2 f3 = __half22float2(a.h[3]), g3 = __half22float2(b.h[3]);
            s12[0] = f0.x + g0.x; s12[1] = f0.y + g0.y;
            s12[2] = f1.x + g1.x; s12[3] = f1.y + g1.y;
            s12[4] = f2.x + g2.x; s12[5] = f2.y + g2.y;
            s12[6] = f3.x + g3.x; s12[7] = f3.y + g3.y;
        }
        float4 o0, o1;
        o0.x = e0.x + rd * s12[0] + dinv * v[0];
        o0.y = e0.y + rd * s12[1] + dinv * v[1];
        o0.z = e0.z + rd * s12[2] + dinv * v[2];
        o0.w = e0.w + rd * s12[3] + dinv * v[3];
        o1.x = e1.x + rd * s12[4] + dinv * v[4];
        o1.y = e1.y + rd * s12[5] + dinv * v[5];
        o1.z = e1.z + rd * s12[6] + dinv * v[6];
        o1.w = e1.w + rd * s12[7] + dinv * v[7];
        float4* ap = (float4*)(d_acc + (size_t)node * 64 + ch * 8);
        __stcs(ap, o0);
        __stcs(ap + 1, o1);
    }
}

// ---------------- KL over all rows -----------------------------------------
__global__ void k_kl(const float* __restrict__ lin_w, const float* __restrict__ lin_b) {
    __shared__ float Wt[32 * 64];
    __shared__ float Bsh[64];
    __shared__ float warpsum[8];
    int tid = threadIdx.x;
    for (int i = tid; i < 2048; i += 256) {
        int d = i >> 5, tt = i & 31;
        Wt[tt * 64 + d] = lin_w[i];
    }
    if (tid < 64) Bsh[tid] = lin_b[tid];
    __syncthreads();
    int w = tid >> 5, lane = tid & 31;
    float local = 0.f;
    for (int it = 0; it < 4; it++) {
        int row = blockIdx.x * 32 + w * 4 + it;
        if (row < NN) {
            float a0 = d_acc[row * 64 + lane];
            float a1 = d_acc[row * 64 + 32 + lane];
            float sp = softplus_f(a0);
            float s0 = 0.f, s1 = 0.f;
            #pragma unroll
            for (int tt = 0; tt < 32; tt++) {
                float spt = __shfl_sync(0xffffffffu, sp, tt);
                s0 += spt * Wt[tt * 64 + lane];
                s1 += spt * Wt[tt * 64 + 32 + lane];
            }
            s0 += Bsh[lane] + 1e-8f;
            s1 += Bsh[lane + 32] + 1e-8f;
            float k0 = -0.5f * (1.f + 2.f * s0 - a0 * a0 - expf(2.f * s0));
            float k1 = -0.5f * (1.f + 2.f * s1 - a1 * a1 - expf(2.f * s1));
            if (!isfinite(k0)) k0 = 0.f;
            if (!isfinite(k1)) k1 = 0.f;
            local += k0 + k1;
        }
    }
    #pragma unroll
    for (int o = 16; o; o >>= 1) local += __shfl_xor_sync(0xffffffffu, local, o);
    if (lane == 0) warpsum[w] = local;
    __syncthreads();
    if (tid == 0) {
        float s = 0.f;
        for (int i = 0; i < 8; i++) s += warpsum[i];
        atomicAdd(&d_sums[0], (double)s);
    }
}

__global__ void k_bpr_emb(const float* __restrict__ ue, const float* __restrict__ ie,
                          const int* __restrict__ users, const int* __restrict__ pos,
                          const int* __restrict__ neg) {
    __shared__ float sb[8], se[8];
    int w = threadIdx.x >> 5, lane = threadIdx.x & 31;
    int b = blockIdx.x * 8 + w;
    float bpr = 0.f, emb = 0.f;
    {
        int u = users[b], pi = pos[b], ni = neg[b];
        float u0 = d_acc[u * 64 + lane],         u1 = d_acc[u * 64 + 32 + lane];
        float p0 = d_acc[(NU + pi) * 64 + lane], p1 = d_acc[(NU + pi) * 64 + 32 + lane];
        float n0 = d_acc[(NU + ni) * 64 + lane], n1 = d_acc[(NU + ni) * 64 + 32 + lane];
        float dsc = (u0 * n0 + u1 * n1) - (u0 * p0 + u1 * p1);
        float r0 = ue[u * 64 + lane],  r1 = ue[u * 64 + 32 + lane];
        float q0 = ie[pi * 64 + lane], q1 = ie[pi * 64 + 32 + lane];
        float m0 = ie[ni * 64 + lane], m1 = ie[ni * 64 + 32 + lane];
        float sq = r0 * r0 + r1 * r1 + q0 * q0 + q1 * q1 + m0 * m0 + m1 * m1;
        #pragma unroll
        for (int o = 16; o; o >>= 1) {
            dsc += __shfl_xor_sync(0xffffffffu, dsc, o);
            sq  += __shfl_xor_sync(0xffffffffu, sq, o);
        }
        if (lane == 0) { bpr = softplus_f(dsc); emb = sq; }
    }
    if (lane == 0) { sb[w] = bpr; se[w] = emb; }
    __syncthreads();
    if (threadIdx.x == 0) {
        float s1 = 0.f, s2 = 0.f;
        for (int i = 0; i < 8; i++) { s1 += sb[i]; s2 += se[i]; }
        atomicAdd(&d_sums[1], (double)s1);
        atomicAdd(&d_sums[2], (double)s2);
    }
}

// ---------------- build normalized CL rows (16 samples / block) ------------
__global__ void k_build_cl(const float* __restrict__ u_int_w, const float* __restrict__ i_int_w,
                           const float* __restrict__ lin_w, const float* __restrict__ lin_b,
                           const float* __restrict__ eps,
                           const int* __restrict__ users, const int* __restrict__ pos) {
    __shared__ float sI[64 * 129];
    __shared__ float sA[64];
    __shared__ float sSp[32];
    __shared__ float sP[128];
    __shared__ float sRed[128];
    __shared__ float sG[64], sO[64];
    int tid = threadIdx.x;
    int s = blockIdx.y;
    const float* intent = s ? i_int_w : u_int_w;

    for (int i = tid; i < 8192; i += 128)
        sI[(i >> 7) * 129 + (i & 127)] = intent[i];

    for (int bi = 0; bi < 16; bi++) {
        int b = blockIdx.x * 16 + bi;
        int r = s ? (NU + pos[b]) : users[b];
        if (tid < 64) sA[tid] = d_acc[r * 64 + tid];
        __syncthreads();
        if (tid < 32) sSp[tid] = softplus_f(sA[tid]);

        float lg = 0.f;
        #pragma unroll 8
        for (int d = 0; d < 64; d++) lg += sA[d] * sI[d * 129 + tid];

        sRed[tid] = lg; __syncthreads();
        for (int o = 64; o; o >>= 1) { if (tid < o) sRed[tid] = fmaxf(sRed[tid], sRed[tid + o]); __syncthreads(); }
        float mx = sRed[0]; __syncthreads();
        float pe = expf(lg - mx);
        sRed[tid] = pe; __syncthreads();
        for (int o = 64; o; o >>= 1) { if (tid < o) sRed[tid] += sRed[tid + o]; __syncthreads(); }
        float psum = sRed[0];
        sP[tid] = pe / psum;
        __syncthreads();

        float genv = 0.f, ov = 0.f;
        if (tid < 64) {
            #pragma unroll 8
            for (int k = 0; k < 128; k++) ov += sP[k] * sI[tid * 129 + k];
            float sd = 1e-8f + lin_b[tid];
            #pragma unroll
            for (int tt = 0; tt < 32; tt++) sd += sSp[tt] * lin_w[tid * 32 + tt];
            genv = sA[tid] + eps[r * 64 + tid] * sd;
            sG[tid] = genv * genv;
            sO[tid] = ov * ov;
        }
        __syncthreads();
        for (int o = 32; o; o >>= 1) { if (tid < o) { sG[tid] += sG[tid + o]; sO[tid] += sO[tid + o]; } __syncthreads(); }
        float gn = rsqrtf(sG[0]), on = rsqrtf(sO[0]);
        if (tid < 64) {
            float gnv = genv * gn, onv = ov * on;
            d_genH[(s * BB + b) * 64 + tid] = __float2half(gnv);
            d_intH[(s * BB + b) * 64 + tid] = __float2half(onv);
            sRed[tid] = gnv * onv;
        } else sRed[tid] = 0.f;
        __syncthreads();
        for (int o = 64; o; o >>= 1) { if (tid < o) sRed[tid] += sRed[tid + o]; __syncthreads(); }
        if (tid == 0) d_posS[s * BB + b] = sRed[0];
        __syncthreads();
    }
}

// ---------------- InfoNCE denominators via HMMA ----------------------------
// grid (32 rowtiles, 32 coltiles, 2 sides), 256 threads = 8 warps (2x4).
// block tile 128x128, warp tile 64x32, swizzled smem + ldmatrix.
__global__ __launch_bounds__(256, 1) void k_infonce_mma() {
    __shared__ __align__(16) __half sA[128 * 64];
    __shared__ __align__(16) __half sB[128 * 64];
    int s = blockIdx.z;
    int r0 = blockIdx.x * 128;
    int c0 = blockIdx.y * 128;
    const uint4* __restrict__ A  = (const uint4*)(d_genH + (size_t)s * BB * 64);
    const uint4* __restrict__ Bm = (const uint4*)(d_intH + (size_t)s * BB * 64);
    int tid = threadIdx.x;
    unsigned baseA = smem_u32(sA), baseB = smem_u32(sB);

    for (int i = tid; i < 1024; i += 256) {
        int r = i >> 3, c = i & 7;
        unsigned off = (unsigned)(r * 128 + c * 16);
        off ^= (unsigned)((r & 7) << 4);
        *(uint4*)((char*)sA + off) = __ldg(A  + (size_t)(r0 + r) * 8 + c);
        *(uint4*)((char*)sB + off) = __ldg(Bm + (size_t)(c0 + r) * 8 + c);
    }
    __syncthreads();

    int wid = tid >> 5, lane = tid & 31;
    int wr = wid >> 2, wc = wid & 3;     // warp rows: wr*64, cols: wc*32
    float acc[4][4][4];
    #pragma unroll
    for (int i = 0; i < 4; i++)
        #pragma unroll
        for (int j = 0; j < 4; j++)
            #pragma unroll
            for (int q = 0; q < 4; q++) acc[i][j][q] = 0.f;

    int selA = lane >> 3, rinA = lane & 7;
    #pragma unroll
    for (int kc = 0; kc < 64; kc += 16) {
        unsigned af[4][4], bf[4][2];
        #pragma unroll
        for (int mi = 0; mi < 4; mi++) {
            int m = wr * 64 + mi * 16 + (selA & 1) * 8 + rinA;
            unsigned off = (unsigned)(m * 128 + kc * 2 + (selA >> 1) * 16);
            off ^= (unsigned)((m & 7) << 4);
            ldsm_x4(af[mi][0], af[mi][1], af[mi][2], af[mi][3], baseA + off);
        }
        #pragma unroll
        for (int ni = 0; ni < 4; ni++) {
            int n = wc * 32 + ni * 8 + rinA;
            unsigned off = (unsigned)(n * 128 + kc * 2 + ((lane >> 3) & 1) * 16);
            off ^= (unsigned)((n & 7) << 4);
            ldsm_x2(bf[ni][0], bf[ni][1], baseB + off);
        }
        #pragma unroll
        for (int mi = 0; mi < 4; mi++)
            #pragma unroll
            for (int ni = 0; ni < 4; ni++)
                mma16816(acc[mi][ni], af[mi][0], af[mi][1], af[mi][2], af[mi][3],
                         bf[ni][0], bf[ni][1]);
    }

    int quad = lane & 3, rr = lane >> 2;
    #pragma unroll
    for (int mi = 0; mi < 4; mi++) {
        float s0 = 0.f, s1 = 0.f;
        #pragma unroll
        for (int ni = 0; ni < 4; ni++) {
            s0 += __expf(acc[mi][ni][0] * 5.0f) + __expf(acc[mi][ni][1] * 5.0f);
            s1 += __expf(acc[mi][ni][2] * 5.0f) + __expf(acc[mi][ni][3] * 5.0f);
        }
        s0 += __shfl_xor_sync(0xffffffffu, s0, 1);
        s0 += __shfl_xor_sync(0xffffffffu, s0, 2);
        s1 += __shfl_xor_sync(0xffffffffu, s1, 1);
        s1 += __shfl_xor_sync(0xffffffffu, s1, 2);
        if (quad == 0) {
            int row = r0 + wr * 64 + mi * 16 + rr;
            atomicAdd(&d_negS[s * BB + row], s0);
            atomicAdd(&d_negS[s * BB + row + 8], s1);
        }
    }
}

__global__ void k_final(const float* __restrict__ ui, const float* __restrict__ ii,
                        float* __restrict__ out) {
    __shared__ double sh[256];
    __shared__ double sh2[256];
    int tid = threadIdx.x;
    double isum = 0.0, clsum = 0.0;
    for (int i = tid; i < 8192; i += 256) {
        float a = ui[i], b2 = ii[i];
        isum += (double)a * a + (double)b2 * b2;
    }
    for (int i = tid; i < 2 * BB; i += 256) {
        float ng = d_negS[i];
        d_negS[i] = 0.f;                       // recycle for next replay
        float p  = expf(d_posS[i] * 5.0f);
        clsum += -(double)logf(p / (ng + 1e-8f) + 1e-8f);
    }
    sh[tid] = isum; sh2[tid] = clsum;
    __syncthreads();
    for (int o = 128; o; o >>= 1) {
        if (tid < o) { sh[tid] += sh[tid + o]; sh2[tid] += sh2[tid + o]; }
        __syncthreads();
    }
    if (tid == 0) {
        double kl = d_sums[0], bpr = d_sums[1], emb = d_sums[2];
        out[0] = (float)(bpr / 4096.0 + 0.01 * (kl / 150000.0));
        out[1] = (float)(0.1 * (sh2[0] / 4096.0));
        out[2] = (float)(1e-5 * emb);
        out[3] = (float)(1e-5 * sh[0]);
        d_sums[0] = 0.0; d_sums[1] = 0.0; d_sums[2] = 0.0;   // recycle
    }
}

// ---------------- launch ---------------------------------------------------
extern "C" void kernel_launch(void* const* d_in, const int* in_sizes, int n_in,
                              void* d_out, int out_size) {
    (void)n_in; (void)out_size;
    const float* user_emb = (const float*)d_in[0];
    const float* item_emb = (const float*)d_in[1];
    const float* user_int = (const float*)d_in[2];
    const float* item_int = (const float*)d_in[3];
    const float* lin_w    = (const float*)d_in[4];
    const float* lin_b    = (const float*)d_in[5];
    const float* eps      = (const float*)d_in[6];
    const int*   h        = (const int*)d_in[7];
    const int*   t        = (const int*)d_in[8];
    const int*   users    = (const int*)d_in[9];
    const int*   pos      = (const int*)d_in[10];
    const int*   neg      = (const int*)d_in[11];
    int E = in_sizes[7];
    float* out = (float*)d_out;

    k_count<<<(E + 255) / 256, 256>>>(h, E);
    kA_bsum<<<NBLK, 256>>>();
    kB_scan<<<1, 1024>>>(E);
    kC_fill<<<NBLK, 256>>>((const float4*)user_emb, (const float4*)item_emb);
    k_bin<<<(E + 255) / 256, 256>>>(h, t, E);

    int gb = NN * 32 / 256;   // 18750 blocks, warp per node (exact)
    k_gather<<<gb, 256>>>((const float4*)user_emb, (const float4*)item_emb, 0);
    k_gather<<<gb, 256>>>((const float4*)user_emb, (const float4*)item_emb, 1);
    k_gather<<<gb, 256>>>((const float4*)user_emb, (const float4*)item_emb, 2);

    k_kl<<<(NN + 31) / 32, 256>>>(lin_w, lin_b);
    k_bpr_emb<<<BB / 8, 256>>>(user_emb, item_emb, users, pos, neg);
    k_build_cl<<<dim3(BB / 16, 2), 128>>>(user_int, item_int, lin_w, lin_b, eps, users, pos);
    k_infonce_mma<<<dim3(32, 32, 2), 256>>>();
    k_final<<<1, 256>>>(user_int, item_int, out);
}

// round 9
// speedup vs baseline: 2.6096x; 1.1848x over previous
#include <cuda_runtime.h>
#include <cuda_fp16.h>
#include <cuda_bf16.h>
#include <math.h>

#define NU 50000
#define NI 100000
#define NN 150000
#define DD 64
#define BB 4096
#define EMAX 3150000
#define NBLK 586            // ceil(NN/256)

// ---------------- device scratch -------------------------------------------
__device__ float  d_deg[NN];            // dinv = deg^-0.5
__device__ float  d_rdeg[NN];           // sqrt(deg)
__device__ int    d_cnt[NN];            // counts -> cursors (reset by gather p0)
__device__ int    d_bsum[1024];
__device__ int    d_rowptr[NN + 1];
__device__ int    d_et[EMAX];           // CSR-sorted target ids
__device__ __half d_egoh[NN * DD];      // s0 = dinv * ego
__device__ __half d_curh[NN * DD];      // s1
__device__ __half d_nxth[NN * DD];      // s2
__device__ float  d_acc[NN * DD];
__device__ __half d_genH[2 * BB * DD];
__device__ __half d_intH[2 * BB * DD];
__device__ float  d_negS[2 * BB];       // zeroed by k_final after use
__device__ float  d_posS[2 * BB];
__device__ double d_sums[4];            // 0: kl, 1: bpr, 2: emb (zeroed by k_final)

__device__ __forceinline__ float softplus_f(float x) {
    return x > 0.f ? x + log1pf(expf(-x)) : log1pf(expf(x));
}

__device__ __forceinline__ unsigned smem_u32(const void* p) {
    return (unsigned)__cvta_generic_to_shared(p);
}

__device__ __forceinline__ void ldsm_x4(unsigned &r0, unsigned &r1, unsigned &r2, unsigned &r3, unsigned addr) {
    asm volatile("ldmatrix.sync.aligned.m8n8.x4.shared.b16 {%0,%1,%2,%3}, [%4];"
                 : "=r"(r0), "=r"(r1), "=r"(r2), "=r"(r3) : "r"(addr));
}
__device__ __forceinline__ void ldsm_x2(unsigned &r0, unsigned &r1, unsigned addr) {
    asm volatile("ldmatrix.sync.aligned.m8n8.x2.shared.b16 {%0,%1}, [%2];"
                 : "=r"(r0), "=r"(r1) : "r"(addr));
}
__device__ __forceinline__ void mma16816(float* c, unsigned a0, unsigned a1, unsigned a2, unsigned a3,
                                         unsigned b0, unsigned b1) {
    asm volatile("mma.sync.aligned.m16n8k16.row.col.f32.f16.f16.f32 "
                 "{%0,%1,%2,%3}, {%4,%5,%6,%7}, {%8,%9}, {%0,%1,%2,%3};"
                 : "+f"(c[0]), "+f"(c[1]), "+f"(c[2]), "+f"(c[3])
                 : "r"(a0), "r"(a1), "r"(a2), "r"(a3), "r"(b0), "r"(b1));
}

// ---------------- CSR build ------------------------------------------------
__global__ void k_count(const int4* __restrict__ h4, const int* __restrict__ h, int E) {
    int i = blockIdx.x * blockDim.x + threadIdx.x;
    int E4 = E >> 2;
    if (i < E4) {
        int4 q = __ldg(h4 + i);
        atomicAdd(&d_cnt[q.x], 1);
        atomicAdd(&d_cnt[q.y], 1);
        atomicAdd(&d_cnt[q.z], 1);
        atomicAdd(&d_cnt[q.w], 1);
    }
    int tail = E4 * 4 + i;
    if (i < (E & 3)) atomicAdd(&d_cnt[h[tail]], 1);
}

__global__ void kA_bsum() {
    __shared__ int sw[8];
    int tid = threadIdx.x;
    int idx = blockIdx.x * 256 + tid;
    int c = (idx < NN) ? d_cnt[idx] : 0;
    if (idx < NN) {
        float fc = (float)c;
        d_deg[idx] = rsqrtf(fc);
        d_rdeg[idx] = sqrtf(fc);
    }
    int v = c;
    #pragma unroll
    for (int o = 16; o; o >>= 1) v += __shfl_xor_sync(0xffffffffu, v, o);
    if ((tid & 31) == 0) sw[tid >> 5] = v;
    __syncthreads();
    if (tid == 0) {
        int s = 0;
        #pragma unroll
        for (int i = 0; i < 8; i++) s += sw[i];
        d_bsum[blockIdx.x] = s;
    }
}

__global__ void kB_scan(int E) {
    __shared__ int ss[1024];
    int tid = threadIdx.x;
    int v = (tid < NBLK) ? d_bsum[tid] : 0;
    ss[tid] = v;
    __syncthreads();
    for (int o = 1; o < 1024; o <<= 1) {
        int x = ss[tid];
        if (tid >= o) x += ss[tid - o];
        __syncthreads();
        ss[tid] = x;
        __syncthreads();
    }
    if (tid < NBLK) d_bsum[tid] = ss[tid] - v;
    if (tid == 0) d_rowptr[NN] = E;
}

// scan within block -> rowptr/cursors, then convert this block's ego rows to half
__global__ void kC_fill(const float4* __restrict__ ue, const float4* __restrict__ ie) {
    __shared__ int sh[256];
    int tid = threadIdx.x;
    int idx = blockIdx.x * 256 + tid;
    int c = (idx < NN) ? d_cnt[idx] : 0;
    sh[tid] = c;
    __syncthreads();
    for (int o = 1; o < 256; o <<= 1) {
        int x = sh[tid];
        if (tid >= o) x += sh[tid - o];
        __syncthreads();
        sh[tid] = x;
        __syncthreads();
    }
    if (idx < NN) {
        int p = d_bsum[blockIdx.x] + sh[tid] - c;
        d_rowptr[idx] = p;
        d_cnt[idx] = p;
    }
    __syncthreads();
    int base_node = blockIdx.x * 256;
    for (int i = tid; i < 4096; i += 256) {
        int node = base_node + (i >> 4);
        if (node >= NN) continue;
        int ch = i & 15;
        float4 v = (node < NU) ? __ldg(ue + (size_t)node * 16 + ch)
                               : __ldg(ie + (size_t)(node - NU) * 16 + ch);
        float s = d_deg[node];
        union { uint2 u; __half2 h[2]; } o;
        o.h[0] = __floats2half2_rn(s * v.x, s * v.y);
        o.h[1] = __floats2half2_rn(s * v.z, s * v.w);
        ((uint2*)d_egoh)[(size_t)node * 16 + ch] = o.u;
    }
}

__global__ void k_bin(const int4* __restrict__ h4, const int4* __restrict__ t4,
                      const int* __restrict__ h, const int* __restrict__ t, int E) {
    int i = blockIdx.x * blockDim.x + threadIdx.x;
    int E4 = E >> 2;
    if (i < E4) {
        int4 qh = __ldg(h4 + i);
        int4 qt = __ldg(t4 + i);
        d_et[atomicAdd(&d_cnt[qh.x], 1)] = qt.x;
        d_et[atomicAdd(&d_cnt[qh.y], 1)] = qt.y;
        d_et[atomicAdd(&d_cnt[qh.z], 1)] = qt.z;
        d_et[atomicAdd(&d_cnt[qh.w], 1)] = qt.w;
    }
    int tail = E4 * 4 + i;
    if (i < (E & 3)) d_et[atomicAdd(&d_cnt[h[tail]], 1)] = t[tail];
}

// ---------------- pull gather: warp/node, index-prefetch pipeline ----------
__device__ __forceinline__ void add8(float* v, uint4 x) {
    union { uint4 u; __half2 h[4]; } c; c.u = x;
    float2 f;
    f = __half22float2(c.h[0]); v[0] += f.x; v[1] += f.y;
    f = __half22float2(c.h[1]); v[2] += f.x; v[3] += f.y;
    f = __half22float2(c.h[2]); v[4] += f.x; v[5] += f.y;
    f = __half22float2(c.h[3]); v[6] += f.x; v[7] += f.y;
}

__global__ void k_gather(const float4* __restrict__ ue, const float4* __restrict__ ie, int pass) {
    int node = (blockIdx.x * blockDim.x + threadIdx.x) >> 5;
    if (node >= NN) return;
    int lane = threadIdx.x & 31;
    int sub = lane >> 3, ch = lane & 7;
    int beg = __ldg(&d_rowptr[node]);
    int end = __ldg(&d_rowptr[node + 1]);
    const uint4* __restrict__ src =
        (pass == 0) ? (const uint4*)d_egoh :
        (pass == 1) ? (const uint4*)d_curh : (const uint4*)d_nxth;
    float v[8] = {0.f, 0.f, 0.f, 0.f, 0.f, 0.f, 0.f, 0.f};
    int e = beg + sub;
    int t0 = 0, t1 = 0;
    if (e < end) t0 = __ldg(&d_et[e]);
    if (e + 4 < end) t1 = __ldg(&d_et[e + 4]);
    while (e + 4 < end) {
        uint4 x0 = __ldg(src + (size_t)t0 * 8 + ch);
        uint4 x1 = __ldg(src + (size_t)t1 * 8 + ch);
        e += 8;
        int n0 = 0, n1 = 0;
        if (e < end)     n0 = __ldg(&d_et[e]);
        if (e + 4 < end) n1 = __ldg(&d_et[e + 4]);
        add8(v, x0);
        add8(v, x1);
        t0 = n0; t1 = n1;
    }
    if (e < end) {
        add8(v, __ldg(src + (size_t)t0 * 8 + ch));
    }
    // reduce across the 4 edge slots
    #pragma unroll
    for (int j = 0; j < 8; j++) {
        v[j] += __shfl_xor_sync(0xffffffffu, v[j], 8);
        v[j] += __shfl_xor_sync(0xffffffffu, v[j], 16);
    }
    float dinv = __ldg(&d_deg[node]);
    if (pass == 0 && lane == 0) d_cnt[node] = 0;  // recycle for next replay
    if (sub != 0) return;
    if (pass < 2) {
        float s = dinv * dinv;
        union { uint4 u; __half2 h[4]; } o;
        o.h[0] = __floats2half2_rn(s * v[0], s * v[1]);
        o.h[1] = __floats2half2_rn(s * v[2], s * v[3]);
        o.h[2] = __floats2half2_rn(s * v[4], s * v[5]);
        o.h[3] = __floats2half2_rn(s * v[6], s * v[7]);
        uint4* dst = (pass == 0) ? (uint4*)d_curh : (uint4*)d_nxth;
        dst[(size_t)node * 8 + ch] = o.u;
    } else {
        float rd = __ldg(&d_rdeg[node]);
        union { uint4 u; __half2 h[4]; } a, b;
        a.u = __ldg((const uint4*)d_curh + (size_t)node * 8 + ch);
        b.u = __ldg((const uint4*)d_nxth + (size_t)node * 8 + ch);
        const float4* ego = (node < NU) ? (ue + (size_t)node * 16)
                                        : (ie + (size_t)(node - NU) * 16);
        float4 e0 = __ldg(ego + ch * 2);
        float4 e1 = __ldg(ego + ch * 2 + 1);
        float s12[8];
        {
            float2 f0 = __half22float2(a.h[0]), g0 = __half22float2(b.h[0]);
            float2 f1 = __half22float2(a.h[1]), g1 = __half22float2(b.h[1]);
            float2 f2 = __half22float2(a.h[2]), g2 = __half22float2(b.h[2]);
            float2 f3 = __half22float2(a.h[3]), g3 = __half22float2(b.h[3]);
            s12[0] = f0.x + g0.x; s12[1] = f0.y + g0.y;
            s12[2] = f1.x + g1.x; s12[3] = f1.y + g1.y;
            s12[4] = f2.x + g2.x; s12[5] = f2.y + g2.y;
            s12[6] = f3.x + g3.x; s12[7] = f3.y + g3.y;
        }
        float4 o0, o1;
        o0.x = e0.x + rd * s12[0] + dinv * v[0];
        o0.y = e0.y + rd * s12[1] + dinv * v[1];
        o0.z = e0.z + rd * s12[2] + dinv * v[2];
        o0.w = e0.w + rd * s12[3] + dinv * v[3];
        o1.x = e1.x + rd * s12[4] + dinv * v[4];
        o1.y = e1.y + rd * s12[5] + dinv * v[5];
        o1.z = e1.z + rd * s12[6] + dinv * v[6];
        o1.w = e1.w + rd * s12[7] + dinv * v[7];
        float4* ap = (float4*)(d_acc + (size_t)node * 64 + ch * 8);
        __stcs(ap, o0);
        __stcs(ap + 1, o1);
    }
}

// ---------------- KL over all rows -----------------------------------------
__global__ void k_kl(const float* __restrict__ lin_w, const float* __restrict__ lin_b) {
    __shared__ float Wt[32 * 64];
    __shared__ float Bsh[64];
    __shared__ float warpsum[8];
    int tid = threadIdx.x;
    for (int i = tid; i < 2048; i += 256) {
        int d = i >> 5, tt = i & 31;
        Wt[tt * 64 + d] = lin_w[i];
    }
    if (tid < 64) Bsh[tid] = lin_b[tid];
    __syncthreads();
    int w = tid >> 5, lane = tid & 31;
    float local = 0.f;
    for (int it = 0; it < 4; it++) {
        int row = blockIdx.x * 32 + w * 4 + it;
        if (row < NN) {
            float a0 = d_acc[row * 64 + lane];
            float a1 = d_acc[row * 64 + 32 + lane];
            float sp = softplus_f(a0);
            float s0 = 0.f, s1 = 0.f;
            #pragma unroll
            for (int tt = 0; tt < 32; tt++) {
                float spt = __shfl_sync(0xffffffffu, sp, tt);
                s0 += spt * Wt[tt * 64 + lane];
                s1 += spt * Wt[tt * 64 + 32 + lane];
            }
            s0 += Bsh[lane] + 1e-8f;
            s1 += Bsh[lane + 32] + 1e-8f;
            float k0 = -0.5f * (1.f + 2.f * s0 - a0 * a0 - expf(2.f * s0));
            float k1 = -0.5f * (1.f + 2.f * s1 - a1 * a1 - expf(2.f * s1));
            if (!isfinite(k0)) k0 = 0.f;
            if (!isfinite(k1)) k1 = 0.f;
            local += k0 + k1;
        }
    }
    #pragma unroll
    for (int o = 16; o; o >>= 1) local += __shfl_xor_sync(0xffffffffu, local, o);
    if (lane == 0) warpsum[w] = local;
    __syncthreads();
    if (tid == 0) {
        float s = 0.f;
        for (int i = 0; i < 8; i++) s += warpsum[i];
        atomicAdd(&d_sums[0], (double)s);
    }
}

__global__ void k_bpr_emb(const float* __restrict__ ue, const float* __restrict__ ie,
                          const int* __restrict__ users, const int* __restrict__ pos,
                          const int* __restrict__ neg) {
    __shared__ float sb[8], se[8];
    int w = threadIdx.x >> 5, lane = threadIdx.x & 31;
    int b = blockIdx.x * 8 + w;
    float bpr = 0.f, emb = 0.f;
    {
        int u = users[b], pi = pos[b], ni = neg[b];
        float u0 = d_acc[u * 64 + lane],         u1 = d_acc[u * 64 + 32 + lane];
        float p0 = d_acc[(NU + pi) * 64 + lane], p1 = d_acc[(NU + pi) * 64 + 32 + lane];
        float n0 = d_acc[(NU + ni) * 64 + lane], n1 = d_acc[(NU + ni) * 64 + 32 + lane];
        float dsc = (u0 * n0 + u1 * n1) - (u0 * p0 + u1 * p1);
        float r0 = ue[u * 64 + lane],  r1 = ue[u * 64 + 32 + lane];
        float q0 = ie[pi * 64 + lane], q1 = ie[pi * 64 + 32 + lane];
        float m0 = ie[ni * 64 + lane], m1 = ie[ni * 64 + 32 + lane];
        float sq = r0 * r0 + r1 * r1 + q0 * q0 + q1 * q1 + m0 * m0 + m1 * m1;
        #pragma unroll
        for (int o = 16; o; o >>= 1) {
            dsc += __shfl_xor_sync(0xffffffffu, dsc, o);
            sq  += __shfl_xor_sync(0xffffffffu, sq, o);
        }
        if (lane == 0) { bpr = softplus_f(dsc); emb = sq; }
    }
    if (lane == 0) { sb[w] = bpr; se[w] = emb; }
    __syncthreads();
    if (threadIdx.x == 0) {
        float s1 = 0.f, s2 = 0.f;
        for (int i = 0; i < 8; i++) { s1 += sb[i]; s2 += se[i]; }
        atomicAdd(&d_sums[1], (double)s1);
        atomicAdd(&d_sums[2], (double)s2);
    }
}

// ---------------- build CL rows: one warp per sample -----------------------
// grid (256, 2), 128 threads = 4 warps; each warp does 4 samples.
__global__ __launch_bounds__(128) void k_build_cl(
        const float* __restrict__ u_int_w, const float* __restrict__ i_int_w,
        const float* __restrict__ lin_w, const float* __restrict__ lin_b,
        const float* __restrict__ eps,
        const int* __restrict__ users, const int* __restrict__ pos) {
    __shared__ float sI[64 * 129];   // intent [d][k], pitch 129
    __shared__ float sW[64 * 33];    // lin_w  [d][t], pitch 33
    int tid = threadIdx.x;
    int s = blockIdx.y;
    const float* intent = s ? i_int_w : u_int_w;
    for (int i = tid; i < 8192; i += 128)
        sI[(i >> 7) * 129 + (i & 127)] = intent[i];
    for (int i = tid; i < 2048; i += 128)
        sW[(i >> 5) * 33 + (i & 31)] = lin_w[i];
    __syncthreads();

    int wid = tid >> 5, lane = tid & 31;
    float bb0 = __ldg(lin_b + lane), bb1 = __ldg(lin_b + 32 + lane);

    for (int it = 0; it < 4; it++) {
        int b = blockIdx.x * 16 + wid * 4 + it;
        int r = s ? (NU + pos[b]) : users[b];
        float a0 = d_acc[(size_t)r * 64 + lane];
        float a1 = d_acc[(size_t)r * 64 + 32 + lane];

        // logits: lane holds k = {lane, 32+lane, 64+lane, 96+lane}
        float lg0 = 0.f, lg1 = 0.f, lg2 = 0.f, lg3 = 0.f;
        #pragma unroll
        for (int d = 0; d < 64; d++) {
            float ad = __shfl_sync(0xffffffffu, (d < 32) ? a0 : a1, d & 31);
            const float* row = &sI[d * 129 + lane];
            lg0 += ad * row[0];
            lg1 += ad * row[32];
            lg2 += ad * row[64];
            lg3 += ad * row[96];
        }
        float mx = fmaxf(fmaxf(lg0, lg1), fmaxf(lg2, lg3));
        #pragma unroll
        for (int o = 16; o; o >>= 1) mx = fmaxf(mx, __shfl_xor_sync(0xffffffffu, mx, o));
        float p0 = expf(lg0 - mx), p1 = expf(lg1 - mx), p2 = expf(lg2 - mx), p3 = expf(lg3 - mx);
        float ps = p0 + p1 + p2 + p3;
        #pragma unroll
        for (int o = 16; o; o >>= 1) ps += __shfl_xor_sync(0xffffffffu, ps, o);
        float inv = 1.f / ps;
        p0 *= inv; p1 *= inv; p2 *= inv; p3 *= inv;

        // ov_d for d0 = lane, d1 = lane+32
        float ov0 = 0.f, ov1 = 0.f;
        const float* r0p = &sI[lane * 129];
        const float* r1p = &sI[(lane + 32) * 129];
        #pragma unroll
        for (int k = 0; k < 32; k++) {
            float q0 = __shfl_sync(0xffffffffu, p0, k);
            float q1 = __shfl_sync(0xffffffffu, p1, k);
            float q2 = __shfl_sync(0xffffffffu, p2, k);
            float q3 = __shfl_sync(0xffffffffu, p3, k);
            ov0 += q0 * r0p[k] + q1 * r0p[32 + k] + q2 * r0p[64 + k] + q3 * r0p[96 + k];
            ov1 += q0 * r1p[k] + q1 * r1p[32 + k] + q2 * r1p[64 + k] + q3 * r1p[96 + k];
        }

        // std + gen
        float sp = softplus_f(a0);           // t = lane
        float sd0 = 0.f, sd1 = 0.f;
        const float* w0p = &sW[lane * 33];
        const float* w1p = &sW[(lane + 32) * 33];
        #pragma unroll
        for (int t = 0; t < 32; t++) {
            float spt = __shfl_sync(0xffffffffu, sp, t);
            sd0 += spt * w0p[t];
            sd1 += spt * w1p[t];
        }
        sd0 += bb0 + 1e-8f;
        sd1 += bb1 + 1e-8f;
        float g0 = a0 + __ldg(eps + (size_t)r * 64 + lane) * sd0;
        float g1 = a1 + __ldg(eps + (size_t)r * 64 + 32 + lane) * sd1;

        float gn = g0 * g0 + g1 * g1;
        float on = ov0 * ov0 + ov1 * ov1;
        #pragma unroll
        for (int o = 16; o; o >>= 1) {
            gn += __shfl_xor_sync(0xffffffffu, gn, o);
            on += __shfl_xor_sync(0xffffffffu, on, o);
        }
        gn = rsqrtf(gn); on = rsqrtf(on);
        g0 *= gn; g1 *= gn; ov0 *= on; ov1 *= on;
        float pd = g0 * ov0 + g1 * ov1;
        #pragma unroll
        for (int o = 16; o; o >>= 1) pd += __shfl_xor_sync(0xffffffffu, pd, o);

        size_t ob = (size_t)(s * BB + b) * 64;
        d_genH[ob + lane] = __float2half(g0);
        d_genH[ob + 32 + lane] = __float2half(g1);
        d_intH[ob + lane] = __float2half(ov0);
        d_intH[ob + 32 + lane] = __float2half(ov1);
        if (lane == 0) d_posS[s * BB + b] = pd;
    }
}

// ---------------- InfoNCE denominators via HMMA ----------------------------
__global__ __launch_bounds__(256, 1) void k_infonce_mma() {
    __shared__ __align__(16) __half sA[128 * 64];
    __shared__ __align__(16) __half sB[128 * 64];
    int s = blockIdx.z;
    int r0 = blockIdx.x * 128;
    int c0 = blockIdx.y * 128;
    const uint4* __restrict__ A  = (const uint4*)(d_genH + (size_t)s * BB * 64);
    const uint4* __restrict__ Bm = (const uint4*)(d_intH + (size_t)s * BB * 64);
    int tid = threadIdx.x;
    unsigned baseA = smem_u32(sA), baseB = smem_u32(sB);

    for (int i = tid; i < 1024; i += 256) {
        int r = i >> 3, c = i & 7;
        unsigned off = (unsigned)(r * 128 + c * 16);
        off ^= (unsigned)((r & 7) << 4);
        *(uint4*)((char*)sA + off) = __ldg(A  + (size_t)(r0 + r) * 8 + c);
        *(uint4*)((char*)sB + off) = __ldg(Bm + (size_t)(c0 + r) * 8 + c);
    }
    __syncthreads();

    int wid = tid >> 5, lane = tid & 31;
    int wr = wid >> 2, wc = wid & 3;
    float acc[4][4][4];
    #pragma unroll
    for (int i = 0; i < 4; i++)
        #pragma unroll
        for (int j = 0; j < 4; j++)
            #pragma unroll
            for (int q = 0; q < 4; q++) acc[i][j][q] = 0.f;

    int selA = lane >> 3, rinA = lane & 7;
    #pragma unroll
    for (int kc = 0; kc < 64; kc += 16) {
        unsigned af[4][4], bf[4][2];
        #pragma unroll
        for (int mi = 0; mi < 4; mi++) {
            int m = wr * 64 + mi * 16 + (selA & 1) * 8 + rinA;
            unsigned off = (unsigned)(m * 128 + kc * 2 + (selA >> 1) * 16);
            off ^= (unsigned)((m & 7) << 4);
            ldsm_x4(af[mi][0], af[mi][1], af[mi][2], af[mi][3], baseA + off);
        }
        #pragma unroll
        for (int ni = 0; ni < 4; ni++) {
            int n = wc * 32 + ni * 8 + rinA;
            unsigned off = (unsigned)(n * 128 + kc * 2 + ((lane >> 3) & 1) * 16);
            off ^= (unsigned)((n & 7) << 4);
            ldsm_x2(bf[ni][0], bf[ni][1], baseB + off);
        }
        #pragma unroll
        for (int mi = 0; mi < 4; mi++)
            #pragma unroll
            for (int ni = 0; ni < 4; ni++)
                mma16816(acc[mi][ni], af[mi][0], af[mi][1], af[mi][2], af[mi][3],
                         bf[ni][0], bf[ni][1]);
    }

    int quad = lane & 3, rr = lane >> 2;
    #pragma unroll
    for (int mi = 0; mi < 4; mi++) {
        float s0 = 0.f, s1 = 0.f;
        #pragma unroll
        for (int ni = 0; ni < 4; ni++) {
            s0 += __expf(acc[mi][ni][0] * 5.0f) + __expf(acc[mi][ni][1] * 5.0f);
            s1 += __expf(acc[mi][ni][2] * 5.0f) + __expf(acc[mi][ni][3] * 5.0f);
        }
        s0 += __shfl_xor_sync(0xffffffffu, s0, 1);
        s0 += __shfl_xor_sync(0xffffffffu, s0, 2);
        s1 += __shfl_xor_sync(0xffffffffu, s1, 1);
        s1 += __shfl_xor_sync(0xffffffffu, s1, 2);
        if (quad == 0) {
            int row = r0 + wr * 64 + mi * 16 + rr;
            atomicAdd(&d_negS[s * BB + row], s0);
            atomicAdd(&d_negS[s * BB + row + 8], s1);
        }
    }
}

__global__ void k_final(const float* __restrict__ ui, const float* __restrict__ ii,
                        float* __restrict__ out) {
    __shared__ double sh[256];
    __shared__ double sh2[256];
    int tid = threadIdx.x;
    double isum = 0.0, clsum = 0.0;
    for (int i = tid; i < 8192; i += 256) {
        float a = ui[i], b2 = ii[i];
        isum += (double)a * a + (double)b2 * b2;
    }
    for (int i = tid; i < 2 * BB; i += 256) {
        float ng = d_negS[i];
        d_negS[i] = 0.f;                       // recycle for next replay
        float p  = expf(d_posS[i] * 5.0f);
        clsum += -(double)logf(p / (ng + 1e-8f) + 1e-8f);
    }
    sh[tid] = isum; sh2[tid] = clsum;
    __syncthreads();
    for (int o = 128; o; o >>= 1) {
        if (tid < o) { sh[tid] += sh[tid + o]; sh2[tid] += sh2[tid + o]; }
        __syncthreads();
    }
    if (tid == 0) {
        double kl = d_sums[0], bpr = d_sums[1], emb = d_sums[2];
        out[0] = (float)(bpr / 4096.0 + 0.01 * (kl / 150000.0));
        out[1] = (float)(0.1 * (sh2[0] / 4096.0));
        out[2] = (float)(1e-5 * emb);
        out[3] = (float)(1e-5 * sh[0]);
        d_sums[0] = 0.0; d_sums[1] = 0.0; d_sums[2] = 0.0;   // recycle
    }
}

// ---------------- launch ---------------------------------------------------
extern "C" void kernel_launch(void* const* d_in, const int* in_sizes, int n_in,
                              void* d_out, int out_size) {
    (void)n_in; (void)out_size;
    const float* user_emb = (const float*)d_in[0];
    const float* item_emb = (const float*)d_in[1];
    const float* user_int = (const float*)d_in[2];
    const float* item_int = (const float*)d_in[3];
    const float* lin_w    = (const float*)d_in[4];
    const float* lin_b    = (const float*)d_in[5];
    const float* eps      = (const float*)d_in[6];
    const int*   h        = (const int*)d_in[7];
    const int*   t        = (const int*)d_in[8];
    const int*   users    = (const int*)d_in[9];
    const int*   pos      = (const int*)d_in[10];
    const int*   neg      = (const int*)d_in[11];
    int E = in_sizes[7];
    float* out = (float*)d_out;

    int e4b = ((E >> 2) + 255) / 256;
    k_count<<<e4b, 256>>>((const int4*)h, h, E);
    kA_bsum<<<NBLK, 256>>>();
    kB_scan<<<1, 1024>>>(E);
    kC_fill<<<NBLK, 256>>>((const float4*)user_emb, (const float4*)item_emb);
    k_bin<<<e4b, 256>>>((const int4*)h, (const int4*)t, h, t, E);

    int gb = NN * 32 / 256;
    k_gather<<<gb, 256>>>((const float4*)user_emb, (const float4*)item_emb, 0);
    k_gather<<<gb, 256>>>((const float4*)user_emb, (const float4*)item_emb, 1);
    k_gather<<<gb, 256>>>((const float4*)user_emb, (const float4*)item_emb, 2);

    k_kl<<<(NN + 31) / 32, 256>>>(lin_w, lin_b);
    k_bpr_emb<<<BB / 8, 256>>>(user_emb, item_emb, users, pos, neg);
    k_build_cl<<<dim3(BB / 16, 2), 128>>>(user_int, item_int, lin_w, lin_b, eps, users, pos);
    k_infonce_mma<<<dim3(32, 32, 2), 256>>>();
    k_final<<<1, 256>>>(user_int, item_int, out);
}

// round 10
// speedup vs baseline: 2.8498x; 1.0920x over previous
#include <cuda_runtime.h>
#include <cuda_fp16.h>
#include <cuda_bf16.h>
#include <math.h>

#define NU 50000
#define NI 100000
#define NN 150000
#define DD 64
#define BB 4096
#define EMAX 3150000
#define NBLK 586            // ceil(NN/256)

// ---------------- device scratch -------------------------------------------
__device__ float  d_deg[NN];            // dinv = deg^-0.5
__device__ float  d_rdeg[NN];           // sqrt(deg)
__device__ int    d_cnt[NN];            // counts -> cursors (reset by gather p0)
__device__ int    d_rowptr[NN];         // row start
__device__ int    d_rend[NN];           // row end
__device__ int    d_cursor = 0;         // global CSR allocation cursor
__device__ int    d_et[EMAX];           // CSR-sorted target ids
__device__ __half d_egoh[NN * DD];      // s0 = dinv * ego
__device__ __half d_curh[NN * DD];      // s1
__device__ __half d_nxth[NN * DD];      // s2
__device__ float  d_acc[NN * DD];
__device__ __half d_genH[2 * BB * DD];
__device__ __half d_intH[2 * BB * DD];
__device__ float  d_negS[2 * BB];       // zeroed by k_final after use
__device__ float  d_posS[2 * BB];
__device__ double d_sums[4];            // 0: kl, 1: bpr, 2: emb (zeroed by k_final)

__device__ __forceinline__ float softplus_f(float x) {
    return x > 0.f ? x + log1pf(expf(-x)) : log1pf(expf(x));
}

__device__ __forceinline__ unsigned smem_u32(const void* p) {
    return (unsigned)__cvta_generic_to_shared(p);
}

__device__ __forceinline__ void ldsm_x4(unsigned &r0, unsigned &r1, unsigned &r2, unsigned &r3, unsigned addr) {
    asm volatile("ldmatrix.sync.aligned.m8n8.x4.shared.b16 {%0,%1,%2,%3}, [%4];"
                 : "=r"(r0), "=r"(r1), "=r"(r2), "=r"(r3) : "r"(addr));
}
__device__ __forceinline__ void ldsm_x2(unsigned &r0, unsigned &r1, unsigned addr) {
    asm volatile("ldmatrix.sync.aligned.m8n8.x2.shared.b16 {%0,%1}, [%2];"
                 : "=r"(r0), "=r"(r1) : "r"(addr));
}
__device__ __forceinline__ void mma16816(float* c, unsigned a0, unsigned a1, unsigned a2, unsigned a3,
                                         unsigned b0, unsigned b1) {
    asm volatile("mma.sync.aligned.m16n8k16.row.col.f32.f16.f16.f32 "
                 "{%0,%1,%2,%3}, {%4,%5,%6,%7}, {%8,%9}, {%0,%1,%2,%3};"
                 : "+f"(c[0]), "+f"(c[1]), "+f"(c[2]), "+f"(c[3])
                 : "r"(a0), "r"(a1), "r"(a2), "r"(a3), "r"(b0), "r"(b1));
}

// ---------------- CSR build ------------------------------------------------
__global__ void k_count(const int4* __restrict__ h4, const int* __restrict__ h, int E) {
    int i = blockIdx.x * blockDim.x + threadIdx.x;
    int E4 = E >> 2;
    if (i < E4) {
        int4 q = __ldg(h4 + i);
        atomicAdd(&d_cnt[q.x], 1);
        atomicAdd(&d_cnt[q.y], 1);
        atomicAdd(&d_cnt[q.z], 1);
        atomicAdd(&d_cnt[q.w], 1);
    }
    int tail = E4 * 4 + i;
    if (i < (E & 3)) atomicAdd(&d_cnt[h[tail]], 1);
}

// block scan + atomic block base (CSR row order is arbitrary but consistent),
// then convert this block's ego rows to half.
__global__ void k_scanfill(const float4* __restrict__ ue, const float4* __restrict__ ie) {
    __shared__ int sh[256];
    __shared__ int sbase;
    __shared__ float sdeg[256];
    int tid = threadIdx.x;
    int idx = blockIdx.x * 256 + tid;
    int c = (idx < NN) ? d_cnt[idx] : 0;
    sh[tid] = c;
    __syncthreads();
    for (int o = 1; o < 256; o <<= 1) {
        int x = sh[tid];
        if (tid >= o) x += sh[tid - o];
        __syncthreads();
        sh[tid] = x;
        __syncthreads();
    }
    if (tid == 255) sbase = atomicAdd(&d_cursor, sh[255]);
    __syncthreads();
    float dinv = rsqrtf((float)c);
    if (idx < NN) {
        int p = sbase + sh[tid] - c;
        d_rowptr[idx] = p;
        d_rend[idx] = p + c;
        d_cnt[idx] = p;                 // cursor for binning
        d_deg[idx] = dinv;
        d_rdeg[idx] = sqrtf((float)c);
    }
    sdeg[tid] = dinv;
    __syncthreads();
    int base_node = blockIdx.x * 256;
    for (int i = tid; i < 4096; i += 256) {
        int node = base_node + (i >> 4);
        if (node >= NN) continue;
        int ch = i & 15;
        float4 v = (node < NU) ? __ldg(ue + (size_t)node * 16 + ch)
                               : __ldg(ie + (size_t)(node - NU) * 16 + ch);
        float s = sdeg[i >> 4];
        union { uint2 u; __half2 h[2]; } o;
        o.h[0] = __floats2half2_rn(s * v.x, s * v.y);
        o.h[1] = __floats2half2_rn(s * v.z, s * v.w);
        ((uint2*)d_egoh)[(size_t)node * 16 + ch] = o.u;
    }
}

__global__ void k_bin(const int4* __restrict__ h4, const int4* __restrict__ t4,
                      const int* __restrict__ h, const int* __restrict__ t, int E) {
    int i = blockIdx.x * blockDim.x + threadIdx.x;
    int E4 = E >> 2;
    if (i < E4) {
        int4 qh = __ldg(h4 + i);
        int4 qt = __ldg(t4 + i);
        d_et[atomicAdd(&d_cnt[qh.x], 1)] = qt.x;
        d_et[atomicAdd(&d_cnt[qh.y], 1)] = qt.y;
        d_et[atomicAdd(&d_cnt[qh.z], 1)] = qt.z;
        d_et[atomicAdd(&d_cnt[qh.w], 1)] = qt.w;
    }
    int tail = E4 * 4 + i;
    if (i < (E & 3)) d_et[atomicAdd(&d_cnt[h[tail]], 1)] = t[tail];
}

// ---------------- pull gather: warp/node, index-prefetch pipeline ----------
__device__ __forceinline__ void add8(float* v, uint4 x) {
    union { uint4 u; __half2 h[4]; } c; c.u = x;
    float2 f;
    f = __half22float2(c.h[0]); v[0] += f.x; v[1] += f.y;
    f = __half22float2(c.h[1]); v[2] += f.x; v[3] += f.y;
    f = __half22float2(c.h[2]); v[4] += f.x; v[5] += f.y;
    f = __half22float2(c.h[3]); v[6] += f.x; v[7] += f.y;
}

template<int PASS>
__global__ void k_gather(const float4* __restrict__ ue, const float4* __restrict__ ie) {
    int node = (blockIdx.x * blockDim.x + threadIdx.x) >> 5;
    int lane = threadIdx.x & 31;
    int sub = lane >> 3, ch = lane & 7;
    int beg = __ldg(&d_rowptr[node]);
    int end = __ldg(&d_rend[node]);
    const uint4* __restrict__ src =
        (PASS == 0) ? (const uint4*)d_egoh :
        (PASS == 1) ? (const uint4*)d_curh : (const uint4*)d_nxth;
    float v[8] = {0.f, 0.f, 0.f, 0.f, 0.f, 0.f, 0.f, 0.f};
    int e = beg + sub;
    int t0 = 0, t1 = 0;
    if (e < end) t0 = __ldg(&d_et[e]);
    if (e + 4 < end) t1 = __ldg(&d_et[e + 4]);
    while (e + 4 < end) {
        uint4 x0 = __ldg(src + (size_t)t0 * 8 + ch);
        uint4 x1 = __ldg(src + (size_t)t1 * 8 + ch);
        e += 8;
        int n0 = 0, n1 = 0;
        if (e < end)     n0 = __ldg(&d_et[e]);
        if (e + 4 < end) n1 = __ldg(&d_et[e + 4]);
        add8(v, x0);
        add8(v, x1);
        t0 = n0; t1 = n1;
    }
    if (e < end) {
        add8(v, __ldg(src + (size_t)t0 * 8 + ch));
    }
    // reduce across the 4 edge slots
    #pragma unroll
    for (int j = 0; j < 8; j++) {
        v[j] += __shfl_xor_sync(0xffffffffu, v[j], 8);
        v[j] += __shfl_xor_sync(0xffffffffu, v[j], 16);
    }
    float dinv = __ldg(&d_deg[node]);
    if (PASS == 0 && lane == 0) d_cnt[node] = 0;  // recycle for next replay
    if (sub != 0) return;
    if (PASS < 2) {
        float s = dinv * dinv;
        union { uint4 u; __half2 h[4]; } o;
        o.h[0] = __floats2half2_rn(s * v[0], s * v[1]);
        o.h[1] = __floats2half2_rn(s * v[2], s * v[3]);
        o.h[2] = __floats2half2_rn(s * v[4], s * v[5]);
        o.h[3] = __floats2half2_rn(s * v[6], s * v[7]);
        uint4* dst = (PASS == 0) ? (uint4*)d_curh : (uint4*)d_nxth;
        dst[(size_t)node * 8 + ch] = o.u;
    } else {
        float rd = __ldg(&d_rdeg[node]);
        union { uint4 u; __half2 h[4]; } a, b;
        a.u = __ldg((const uint4*)d_curh + (size_t)node * 8 + ch);
        b.u = __ldg((const uint4*)d_nxth + (size_t)node * 8 + ch);
        const float4* ego = (node < NU) ? (ue + (size_t)node * 16)
                                        : (ie + (size_t)(node - NU) * 16);
        float4 e0 = __ldg(ego + ch * 2);
        float4 e1 = __ldg(ego + ch * 2 + 1);
        float s12[8];
        {
            float2 f0 = __half22float2(a.h[0]), g0 = __half22float2(b.h[0]);
            float2 f1 = __half22float2(a.h[1]), g1 = __half22float2(b.h[1]);
            float2 f2 = __half22float2(a.h[2]), g2 = __half22float2(b.h[2]);
            float2 f3 = __half22float2(a.h[3]), g3 = __half22float2(b.h[3]);
            s12[0] = f0.x + g0.x; s12[1] = f0.y + g0.y;
            s12[2] = f1.x + g1.x; s12[3] = f1.y + g1.y;
            s12[4] = f2.x + g2.x; s12[5] = f2.y + g2.y;
            s12[6] = f3.x + g3.x; s12[7] = f3.y + g3.y;
        }
        float4 o0, o1;
        o0.x = e0.x + rd * s12[0] + dinv * v[0];
        o0.y = e0.y + rd * s12[1] + dinv * v[1];
        o0.z = e0.z + rd * s12[2] + dinv * v[2];
        o0.w = e0.w + rd * s12[3] + dinv * v[3];
        o1.x = e1.x + rd * s12[4] + dinv * v[4];
        o1.y = e1.y + rd * s12[5] + dinv * v[5];
        o1.z = e1.z + rd * s12[6] + dinv * v[6];
        o1.w = e1.w + rd * s12[7] + dinv * v[7];
        float4* ap = (float4*)(d_acc + (size_t)node * 64 + ch * 8);
        ap[0] = o0;
        ap[1] = o1;
    }
}

// ---------------- KL over all rows: lane-per-row, W broadcast --------------
__global__ __launch_bounds__(256) void k_kl(const float* __restrict__ lin_w,
                                            const float* __restrict__ lin_b) {
    __shared__ float sW[2048];   // [d][t] d*32+t
    __shared__ float sB[64];
    __shared__ float wsum[8];
    int tid = threadIdx.x;
    for (int i = tid; i < 2048; i += 256) sW[i] = lin_w[i];
    if (tid < 64) sB[tid] = lin_b[tid];
    __syncthreads();
    int row = blockIdx.x * 256 + tid;
    float kl = 0.f;
    if (row < NN) {
        const float4* ar = (const float4*)(d_acc + (size_t)row * 64);
        float4 c0[8];
        #pragma unroll
        for (int i = 0; i < 8; i++) c0[i] = __ldg(ar + i);
        float sp[32];
        #pragma unroll
        for (int i = 0; i < 8; i++) {
            sp[4*i+0] = softplus_f(c0[i].x);
            sp[4*i+1] = softplus_f(c0[i].y);
            sp[4*i+2] = softplus_f(c0[i].z);
            sp[4*i+3] = softplus_f(c0[i].w);
        }
        #pragma unroll
        for (int half = 0; half < 2; half++) {
            if (half) {
                #pragma unroll
                for (int i = 0; i < 8; i++) c0[i] = __ldg(ar + 8 + i);
            }
            #pragma unroll
            for (int dq = 0; dq < 8; dq++) {
                float am[4] = {c0[dq].x, c0[dq].y, c0[dq].z, c0[dq].w};
                #pragma unroll
                for (int dj = 0; dj < 4; dj++) {
                    int d = half * 32 + dq * 4 + dj;
                    float s = sB[d] + 1e-8f;
                    #pragma unroll
                    for (int t4 = 0; t4 < 8; t4++) {
                        float4 w = *(const float4*)&sW[d * 32 + t4 * 4];
                        s += sp[4*t4] * w.x + sp[4*t4+1] * w.y
                           + sp[4*t4+2] * w.z + sp[4*t4+3] * w.w;
                    }
                    float k = -0.5f * (1.f + 2.f * s - am[dj] * am[dj] - expf(2.f * s));
                    if (isfinite(k)) kl += k;
                }
            }
        }
    }
    #pragma unroll
    for (int o = 16; o; o >>= 1) kl += __shfl_xor_sync(0xffffffffu, kl, o);
    if ((tid & 31) == 0) wsum[tid >> 5] = kl;
    __syncthreads();
    if (tid == 0) {
        float s = 0.f;
        #pragma unroll
        for (int i = 0; i < 8; i++) s += wsum[i];
        atomicAdd(&d_sums[0], (double)s);
    }
}

__global__ void k_bpr_emb(const float* __restrict__ ue, const float* __restrict__ ie,
                          const int* __restrict__ users, const int* __restrict__ pos,
                          const int* __restrict__ neg) {
    __shared__ float sb[8], se[8];
    int w = threadIdx.x >> 5, lane = threadIdx.x & 31;
    int b = blockIdx.x * 8 + w;
    float bpr = 0.f, emb = 0.f;
    {
        int u = users[b], pi = pos[b], ni = neg[b];
        float u0 = d_acc[u * 64 + lane],         u1 = d_acc[u * 64 + 32 + lane];
        float p0 = d_acc[(NU + pi) * 64 + lane], p1 = d_acc[(NU + pi) * 64 + 32 + lane];
        float n0 = d_acc[(NU + ni) * 64 + lane], n1 = d_acc[(NU + ni) * 64 + 32 + lane];
        float dsc = (u0 * n0 + u1 * n1) - (u0 * p0 + u1 * p1);
        float r0 = ue[u * 64 + lane],  r1 = ue[u * 64 + 32 + lane];
        float q0 = ie[pi * 64 + lane], q1 = ie[pi * 64 + 32 + lane];
        float m0 = ie[ni * 64 + lane], m1 = ie[ni * 64 + 32 + lane];
        float sq = r0 * r0 + r1 * r1 + q0 * q0 + q1 * q1 + m0 * m0 + m1 * m1;
        #pragma unroll
        for (int o = 16; o; o >>= 1) {
            dsc += __shfl_xor_sync(0xffffffffu, dsc, o);
            sq  += __shfl_xor_sync(0xffffffffu, sq, o);
        }
        if (lane == 0) { bpr = softplus_f(dsc); emb = sq; }
    }
    if (lane == 0) { sb[w] = bpr; se[w] = emb; }
    __syncthreads();
    if (threadIdx.x == 0) {
        float s1 = 0.f, s2 = 0.f;
        for (int i = 0; i < 8; i++) { s1 += sb[i]; s2 += se[i]; }
        atomicAdd(&d_sums[1], (double)s1);
        atomicAdd(&d_sums[2], (double)s2);
    }
}

// ---------------- build CL rows: one warp per sample -----------------------
__global__ __launch_bounds__(128) void k_build_cl(
        const float* __restrict__ u_int_w, const float* __restrict__ i_int_w,
        const float* __restrict__ lin_w, const float* __restrict__ lin_b,
        const float* __restrict__ eps,
        const int* __restrict__ users, const int* __restrict__ pos) {
    __shared__ float sI[64 * 129];   // intent [d][k], pitch 129
    __shared__ float sW[64 * 33];    // lin_w  [d][t], pitch 33
    int tid = threadIdx.x;
    int s = blockIdx.y;
    const float* intent = s ? i_int_w : u_int_w;
    for (int i = tid; i < 8192; i += 128)
        sI[(i >> 7) * 129 + (i & 127)] = intent[i];
    for (int i = tid; i < 2048; i += 128)
        sW[(i >> 5) * 33 + (i & 31)] = lin_w[i];
    __syncthreads();

    int wid = tid >> 5, lane = tid & 31;
    float bb0 = __ldg(lin_b + lane), bb1 = __ldg(lin_b + 32 + lane);

    for (int it = 0; it < 4; it++) {
        int b = blockIdx.x * 16 + wid * 4 + it;
        int r = s ? (NU + pos[b]) : users[b];
        float a0 = d_acc[(size_t)r * 64 + lane];
        float a1 = d_acc[(size_t)r * 64 + 32 + lane];

        float lg0 = 0.f, lg1 = 0.f, lg2 = 0.f, lg3 = 0.f;
        #pragma unroll
        for (int d = 0; d < 64; d++) {
            float ad = __shfl_sync(0xffffffffu, (d < 32) ? a0 : a1, d & 31);
            const float* row = &sI[d * 129 + lane];
            lg0 += ad * row[0];
            lg1 += ad * row[32];
            lg2 += ad * row[64];
            lg3 += ad * row[96];
        }
        float mx = fmaxf(fmaxf(lg0, lg1), fmaxf(lg2, lg3));
        #pragma unroll
        for (int o = 16; o; o >>= 1) mx = fmaxf(mx, __shfl_xor_sync(0xffffffffu, mx, o));
        float p0 = expf(lg0 - mx), p1 = expf(lg1 - mx), p2 = expf(lg2 - mx), p3 = expf(lg3 - mx);
        float ps = p0 + p1 + p2 + p3;
        #pragma unroll
        for (int o = 16; o; o >>= 1) ps += __shfl_xor_sync(0xffffffffu, ps, o);
        float inv = 1.f / ps;
        p0 *= inv; p1 *= inv; p2 *= inv; p3 *= inv;

        float ov0 = 0.f, ov1 = 0.f;
        const float* r0p = &sI[lane * 129];
        const float* r1p = &sI[(lane + 32) * 129];
        #pragma unroll
        for (int k = 0; k < 32; k++) {
            float q0 = __shfl_sync(0xffffffffu, p0, k);
            float q1 = __shfl_sync(0xffffffffu, p1, k);
            float q2 = __shfl_sync(0xffffffffu, p2, k);
            float q3 = __shfl_sync(0xffffffffu, p3, k);
            ov0 += q0 * r0p[k] + q1 * r0p[32 + k] + q2 * r0p[64 + k] + q3 * r0p[96 + k];
            ov1 += q0 * r1p[k] + q1 * r1p[32 + k] + q2 * r1p[64 + k] + q3 * r1p[96 + k];
        }

        float sp = softplus_f(a0);
        float sd0 = 0.f, sd1 = 0.f;
        const float* w0p = &sW[lane * 33];
        const float* w1p = &sW[(lane + 32) * 33];
        #pragma unroll
        for (int t = 0; t < 32; t++) {
            float spt = __shfl_sync(0xffffffffu, sp, t);
            sd0 += spt * w0p[t];
            sd1 += spt * w1p[t];
        }
        sd0 += bb0 + 1e-8f;
        sd1 += bb1 + 1e-8f;
        float g0 = a0 + __ldg(eps + (size_t)r * 64 + lane) * sd0;
        float g1 = a1 + __ldg(eps + (size_t)r * 64 + 32 + lane) * sd1;

        float gn = g0 * g0 + g1 * g1;
        float on = ov0 * ov0 + ov1 * ov1;
        #pragma unroll
        for (int o = 16; o; o >>= 1) {
            gn += __shfl_xor_sync(0xffffffffu, gn, o);
            on += __shfl_xor_sync(0xffffffffu, on, o);
        }
        gn = rsqrtf(gn); on = rsqrtf(on);
        g0 *= gn; g1 *= gn; ov0 *= on; ov1 *= on;
        float pd = g0 * ov0 + g1 * ov1;
        #pragma unroll
        for (int o = 16; o; o >>= 1) pd += __shfl_xor_sync(0xffffffffu, pd, o);

        size_t ob = (size_t)(s * BB + b) * 64;
        d_genH[ob + lane] = __float2half(g0);
        d_genH[ob + 32 + lane] = __float2half(g1);
        d_intH[ob + lane] = __float2half(ov0);
        d_intH[ob + 32 + lane] = __float2half(ov1);
        if (lane == 0) d_posS[s * BB + b] = pd;
    }
}

// ---------------- InfoNCE denominators via HMMA ----------------------------
__global__ __launch_bounds__(256, 1) void k_infonce_mma() {
    __shared__ __align__(16) __half sA[128 * 64];
    __shared__ __align__(16) __half sB[128 * 64];
    int s = blockIdx.z;
    int r0 = blockIdx.x * 128;
    int c0 = blockIdx.y * 128;
    const uint4* __restrict__ A  = (const uint4*)(d_genH + (size_t)s * BB * 64);
    const uint4* __restrict__ Bm = (const uint4*)(d_intH + (size_t)s * BB * 64);
    int tid = threadIdx.x;
    unsigned baseA = smem_u32(sA), baseB = smem_u32(sB);

    for (int i = tid; i < 1024; i += 256) {
        int r = i >> 3, c = i & 7;
        unsigned off = (unsigned)(r * 128 + c * 16);
        off ^= (unsigned)((r & 7) << 4);
        *(uint4*)((char*)sA + off) = __ldg(A  + (size_t)(r0 + r) * 8 + c);
        *(uint4*)((char*)sB + off) = __ldg(Bm + (size_t)(c0 + r) * 8 + c);
    }
    __syncthreads();

    int wid = tid >> 5, lane = tid & 31;
    int wr = wid >> 2, wc = wid & 3;
    float acc[4][4][4];
    #pragma unroll
    for (int i = 0; i < 4; i++)
        #pragma unroll
        for (int j = 0; j < 4; j++)
            #pragma unroll
            for (int q = 0; q < 4; q++) acc[i][j][q] = 0.f;

    int selA = lane >> 3, rinA = lane & 7;
    #pragma unroll
    for (int kc = 0; kc < 64; kc += 16) {
        unsigned af[4][4], bf[4][2];
        #pragma unroll
        for (int mi = 0; mi < 4; mi++) {
            int m = wr * 64 + mi * 16 + (selA & 1) * 8 + rinA;
            unsigned off = (unsigned)(m * 128 + kc * 2 + (selA >> 1) * 16);
            off ^= (unsigned)((m & 7) << 4);
            ldsm_x4(af[mi][0], af[mi][1], af[mi][2], af[mi][3], baseA + off);
        }
        #pragma unroll
        for (int ni = 0; ni < 4; ni++) {
            int n = wc * 32 + ni * 8 + rinA;
            unsigned off = (unsigned)(n * 128 + kc * 2 + ((lane >> 3) & 1) * 16);
            off ^= (unsigned)((n & 7) << 4);
            ldsm_x2(bf[ni][0], bf[ni][1], baseB + off);
        }
        #pragma unroll
        for (int mi = 0; mi < 4; mi++)
            #pragma unroll
            for (int ni = 0; ni < 4; ni++)
                mma16816(acc[mi][ni], af[mi][0], af[mi][1], af[mi][2], af[mi][3],
                         bf[ni][0], bf[ni][1]);
    }

    int quad = lane & 3, rr = lane >> 2;
    #pragma unroll
    for (int mi = 0; mi < 4; mi++) {
        float s0 = 0.f, s1 = 0.f;
        #pragma unroll
        for (int ni = 0; ni < 4; ni++) {
            s0 += __expf(acc[mi][ni][0] * 5.0f) + __expf(acc[mi][ni][1] * 5.0f);
            s1 += __expf(acc[mi][ni][2] * 5.0f) + __expf(acc[mi][ni][3] * 5.0f);
        }
        s0 += __shfl_xor_sync(0xffffffffu, s0, 1);
        s0 += __shfl_xor_sync(0xffffffffu, s0, 2);
        s1 += __shfl_xor_sync(0xffffffffu, s1, 1);
        s1 += __shfl_xor_sync(0xffffffffu, s1, 2);
        if (quad == 0) {
            int row = r0 + wr * 64 + mi * 16 + rr;
            atomicAdd(&d_negS[s * BB + row], s0);
            atomicAdd(&d_negS[s * BB + row + 8], s1);
        }
    }
}

__global__ void k_final(const float* __restrict__ ui, const float* __restrict__ ii,
                        float* __restrict__ out) {
    __shared__ double sh[256];
    __shared__ double sh2[256];
    int tid = threadIdx.x;
    double isum = 0.0, clsum = 0.0;
    for (int i = tid; i < 8192; i += 256) {
        float a = ui[i], b2 = ii[i];
        isum += (double)a * a + (double)b2 * b2;
    }
    for (int i = tid; i < 2 * BB; i += 256) {
        float ng = d_negS[i];
        d_negS[i] = 0.f;                       // recycle for next replay
        float p  = expf(d_posS[i] * 5.0f);
        clsum += -(double)logf(p / (ng + 1e-8f) + 1e-8f);
    }
    sh[tid] = isum; sh2[tid] = clsum;
    __syncthreads();
    for (int o = 128; o; o >>= 1) {
        if (tid < o) { sh[tid] += sh[tid + o]; sh2[tid] += sh2[tid + o]; }
        __syncthreads();
    }
    if (tid == 0) {
        double kl = d_sums[0], bpr = d_sums[1], emb = d_sums[2];
        out[0] = (float)(bpr / 4096.0 + 0.01 * (kl / 150000.0));
        out[1] = (float)(0.1 * (sh2[0] / 4096.0));
        out[2] = (float)(1e-5 * emb);
        out[3] = (float)(1e-5 * sh[0]);
        d_sums[0] = 0.0; d_sums[1] = 0.0; d_sums[2] = 0.0;   // recycle
        d_cursor = 0;                                        // recycle
    }
}

// ---------------- launch ---------------------------------------------------
extern "C" void kernel_launch(void* const* d_in, const int* in_sizes, int n_in,
                              void* d_out, int out_size) {
    (void)n_in; (void)out_size;
    const float* user_emb = (const float*)d_in[0];
    const float* item_emb = (const float*)d_in[1];
    const float* user_int = (const float*)d_in[2];
    const float* item_int = (const float*)d_in[3];
    const float* lin_w    = (const float*)d_in[4];
    const float* lin_b    = (const float*)d_in[5];
    const float* eps      = (const float*)d_in[6];
    const int*   h        = (const int*)d_in[7];
    const int*   t        = (const int*)d_in[8];
    const int*   users    = (const int*)d_in[9];
    const int*   pos      = (const int*)d_in[10];
    const int*   neg      = (const int*)d_in[11];
    int E = in_sizes[7];
    float* out = (float*)d_out;

    int e4b = ((E >> 2) + 255) / 256;
    k_count<<<e4b, 256>>>((const int4*)h, h, E);
    k_scanfill<<<NBLK, 256>>>((const float4*)user_emb, (const float4*)item_emb);
    k_bin<<<e4b, 256>>>((const int4*)h, (const int4*)t, h, t, E);

    int gb = NN * 32 / 256;
    k_gather<0><<<gb, 256>>>((const float4*)user_emb, (const float4*)item_emb);
    k_gather<1><<<gb, 256>>>((const float4*)user_emb, (const float4*)item_emb);
    k_gather<2><<<gb, 256>>>((const float4*)user_emb, (const float4*)item_emb);

    k_kl<<<NBLK, 256>>>(lin_w, lin_b);
    k_bpr_emb<<<BB / 8, 256>>>(user_emb, item_emb, users, pos, neg);
    k_build_cl<<<dim3(BB / 16, 2), 128>>>(user_int, item_int, lin_w, lin_b, eps, users, pos);
    k_infonce_mma<<<dim3(32, 32, 2), 256>>>();
    k_final<<<1, 256>>>(user_int, item_int, out);
}

// round 13
// speedup vs baseline: 3.0834x; 1.0819x over previous
#include <cuda_runtime.h>
#include <cuda_fp16.h>
#include <cuda_bf16.h>
#include <math.h>

#define NU 50000
#define NI 100000
#define NN 150000
#define DD 64
#define BB 4096
#define EMAX 3150000
#define NBLK 586            // ceil(NN/256)

// ---------------- device scratch -------------------------------------------
__device__ float  d_deg[NN];            // dinv = deg^-0.5
__device__ float  d_rdeg[NN];           // sqrt(deg)
__device__ int    d_cnt[NN];            // counts -> cursors (reset by gather p0)
__device__ int    d_rowptr[NN];         // row start
__device__ int    d_rend[NN];           // row end
__device__ int    d_cursor = 0;         // global CSR allocation cursor
__device__ int    d_et[EMAX];           // CSR-sorted target ids
__device__ __half d_egoh[NN * DD];      // s0 = dinv * ego
__device__ __half d_curh[NN * DD];      // s1
__device__ __half d_nxth[NN * DD];      // s2
__device__ float  d_acc[NN * DD];
__device__ __half d_genH[2 * BB * DD];
__device__ __half d_intH[2 * BB * DD];
__device__ float  d_negS[2 * BB];       // zeroed by k_final after use
__device__ float  d_posS[2 * BB];
__device__ double d_sums[4];            // 0: kl, 1: bpr, 2: emb (zeroed by k_final)

__device__ __forceinline__ float softplus_f(float x) {
    return x > 0.f ? x + log1pf(expf(-x)) : log1pf(expf(x));
}

__device__ __forceinline__ unsigned smem_u32(const void* p) {
    return (unsigned)__cvta_generic_to_shared(p);
}

__device__ __forceinline__ void ldsm_x4(unsigned &r0, unsigned &r1, unsigned &r2, unsigned &r3, unsigned addr) {
    asm volatile("ldmatrix.sync.aligned.m8n8.x4.shared.b16 {%0,%1,%2,%3}, [%4];"
                 : "=r"(r0), "=r"(r1), "=r"(r2), "=r"(r3) : "r"(addr));
}
__device__ __forceinline__ void ldsm_x2(unsigned &r0, unsigned &r1, unsigned addr) {
    asm volatile("ldmatrix.sync.aligned.m8n8.x2.shared.b16 {%0,%1}, [%2];"
                 : "=r"(r0), "=r"(r1) : "r"(addr));
}
__device__ __forceinline__ void mma16816(float* c, unsigned a0, unsigned a1, unsigned a2, unsigned a3,
                                         unsigned b0, unsigned b1) {
    asm volatile("mma.sync.aligned.m16n8k16.row.col.f32.f16.f16.f32 "
                 "{%0,%1,%2,%3}, {%4,%5,%6,%7}, {%8,%9}, {%0,%1,%2,%3};"
                 : "+f"(c[0]), "+f"(c[1]), "+f"(c[2]), "+f"(c[3])
                 : "r"(a0), "r"(a1), "r"(a2), "r"(a3), "r"(b0), "r"(b1));
}

// ---------------- CSR build ------------------------------------------------
__global__ void k_count(const int4* __restrict__ h4, const int* __restrict__ h, int E) {
    int i = blockIdx.x * blockDim.x + threadIdx.x;
    int E4 = E >> 2;
    if (i < E4) {
        int4 q = __ldg(h4 + i);
        atomicAdd(&d_cnt[q.x], 1);
        atomicAdd(&d_cnt[q.y], 1);
        atomicAdd(&d_cnt[q.z], 1);
        atomicAdd(&d_cnt[q.w], 1);
    }
    int tail = E4 * 4 + i;
    if (i < (E & 3)) atomicAdd(&d_cnt[h[tail]], 1);
}

// block scan + atomic block base, then convert this block's ego rows to half.
__global__ void k_scanfill(const float4* __restrict__ ue, const float4* __restrict__ ie) {
    __shared__ int sh[256];
    __shared__ int sbase;
    __shared__ float sdeg[256];
    int tid = threadIdx.x;
    int idx = blockIdx.x * 256 + tid;
    int c = (idx < NN) ? d_cnt[idx] : 0;
    sh[tid] = c;
    __syncthreads();
    for (int o = 1; o < 256; o <<= 1) {
        int x = sh[tid];
        if (tid >= o) x += sh[tid - o];
        __syncthreads();
        sh[tid] = x;
        __syncthreads();
    }
    if (tid == 255) sbase = atomicAdd(&d_cursor, sh[255]);
    __syncthreads();
    float dinv = rsqrtf((float)c);
    if (idx < NN) {
        int p = sbase + sh[tid] - c;
        d_rowptr[idx] = p;
        d_rend[idx] = p + c;
        d_cnt[idx] = p;                 // cursor for binning
        d_deg[idx] = dinv;
        d_rdeg[idx] = sqrtf((float)c);
    }
    sdeg[tid] = dinv;
    __syncthreads();
    int base_node = blockIdx.x * 256;
    for (int i = tid; i < 4096; i += 256) {
        int node = base_node + (i >> 4);
        if (node >= NN) continue;
        int ch = i & 15;
        float4 v = (node < NU) ? __ldg(ue + (size_t)node * 16 + ch)
                               : __ldg(ie + (size_t)(node - NU) * 16 + ch);
        float s = sdeg[i >> 4];
        union { uint2 u; __half2 h[2]; } o;
        o.h[0] = __floats2half2_rn(s * v.x, s * v.y);
        o.h[1] = __floats2half2_rn(s * v.z, s * v.w);
        ((uint2*)d_egoh)[(size_t)node * 16 + ch] = o.u;
    }
}

__global__ void k_bin(const int4* __restrict__ h4, const int4* __restrict__ t4,
                      const int* __restrict__ h, const int* __restrict__ t, int E) {
    int i = blockIdx.x * blockDim.x + threadIdx.x;
    int E4 = E >> 2;
    if (i < E4) {
        int4 qh = __ldg(h4 + i);
        int4 qt = __ldg(t4 + i);
        d_et[atomicAdd(&d_cnt[qh.x], 1)] = qt.x;
        d_et[atomicAdd(&d_cnt[qh.y], 1)] = qt.y;
        d_et[atomicAdd(&d_cnt[qh.z], 1)] = qt.z;
        d_et[atomicAdd(&d_cnt[qh.w], 1)] = qt.w;
    }
    int tail = E4 * 4 + i;
    if (i < (E & 3)) d_et[atomicAdd(&d_cnt[h[tail]], 1)] = t[tail];
}

// ---------------- pull gather: warp/node, HADD2 accumulate -----------------
template<int PASS>
__global__ void k_gather(const float4* __restrict__ ue, const float4* __restrict__ ie) {
    int node = (blockIdx.x * blockDim.x + threadIdx.x) >> 5;
    int lane = threadIdx.x & 31;
    int sub = lane >> 3, ch = lane & 7;
    int beg = __ldg(&d_rowptr[node]);
    int end = __ldg(&d_rend[node]);
    const char* __restrict__ src =
        (PASS == 0) ? (const char*)d_egoh :
        (PASS == 1) ? (const char*)d_curh : (const char*)d_nxth;
    unsigned choff = (unsigned)ch << 4;
    __half2 z2 = __float2half2_rn(0.f);
    __half2 va0 = z2, va1 = z2, va2 = z2, va3 = z2;
    __half2 vb0 = z2, vb1 = z2, vb2 = z2, vb3 = z2;
    int e = beg + sub;
    int t0 = 0, t1 = 0;
    if (e < end) t0 = __ldg(&d_et[e]);
    if (e + 4 < end) t1 = __ldg(&d_et[e + 4]);
    while (e + 4 < end) {
        union { uint4 u; __half2 h[4]; } x0, x1;
        x0.u = __ldg((const uint4*)(src + (((unsigned)t0) << 7) + choff));
        x1.u = __ldg((const uint4*)(src + (((unsigned)t1) << 7) + choff));
        e += 8;
        int n0 = 0, n1 = 0;
        if (e < end)     n0 = __ldg(&d_et[e]);
        if (e + 4 < end) n1 = __ldg(&d_et[e + 4]);
        va0 = __hadd2(va0, x0.h[0]); va1 = __hadd2(va1, x0.h[1]);
        va2 = __hadd2(va2, x0.h[2]); va3 = __hadd2(va3, x0.h[3]);
        vb0 = __hadd2(vb0, x1.h[0]); vb1 = __hadd2(vb1, x1.h[1]);
        vb2 = __hadd2(vb2, x1.h[2]); vb3 = __hadd2(vb3, x1.h[3]);
        t0 = n0; t1 = n1;
    }
    if (e < end) {
        union { uint4 u; __half2 h[4]; } x0;
        x0.u = __ldg((const uint4*)(src + (((unsigned)t0) << 7) + choff));
        va0 = __hadd2(va0, x0.h[0]); va1 = __hadd2(va1, x0.h[1]);
        va2 = __hadd2(va2, x0.h[2]); va3 = __hadd2(va3, x0.h[3]);
    }
    float v[8];
    {
        float2 fa, fb;
        fa = __half22float2(va0); fb = __half22float2(vb0); v[0] = fa.x + fb.x; v[1] = fa.y + fb.y;
        fa = __half22float2(va1); fb = __half22float2(vb1); v[2] = fa.x + fb.x; v[3] = fa.y + fb.y;
        fa = __half22float2(va2); fb = __half22float2(vb2); v[4] = fa.x + fb.x; v[5] = fa.y + fb.y;
        fa = __half22float2(va3); fb = __half22float2(vb3); v[6] = fa.x + fb.x; v[7] = fa.y + fb.y;
    }
    // reduce across the 4 edge slots
    #pragma unroll
    for (int j = 0; j < 8; j++) {
        v[j] += __shfl_xor_sync(0xffffffffu, v[j], 8);
        v[j] += __shfl_xor_sync(0xffffffffu, v[j], 16);
    }
    float dinv = __ldg(&d_deg[node]);
    if (PASS == 0 && lane == 0) d_cnt[node] = 0;  // recycle for next replay
    if (sub != 0) return;
    if (PASS < 2) {
        float s = dinv * dinv;
        union { uint4 u; __half2 h[4]; } o;
        o.h[0] = __floats2half2_rn(s * v[0], s * v[1]);
        o.h[1] = __floats2half2_rn(s * v[2], s * v[3]);
        o.h[2] = __floats2half2_rn(s * v[4], s * v[5]);
        o.h[3] = __floats2half2_rn(s * v[6], s * v[7]);
        uint4* dst = (PASS == 0) ? (uint4*)d_curh : (uint4*)d_nxth;
        dst[(size_t)node * 8 + ch] = o.u;
    } else {
        float rd = __ldg(&d_rdeg[node]);
        union { uint4 u; __half2 h[4]; } a, b;
        a.u = __ldg((const uint4*)d_curh + (size_t)node * 8 + ch);
        b.u = __ldg((const uint4*)d_nxth + (size_t)node * 8 + ch);
        const float4* ego = (node < NU) ? (ue + (size_t)node * 16)
                                        : (ie + (size_t)(node - NU) * 16);
        float4 e0 = __ldg(ego + ch * 2);
        float4 e1 = __ldg(ego + ch * 2 + 1);
        float s12[8];
        {
            float2 f0 = __half22float2(a.h[0]), g0 = __half22float2(b.h[0]);
            float2 f1 = __half22float2(a.h[1]), g1 = __half22float2(b.h[1]);
            float2 f2 = __half22float2(a.h[2]), g2 = __half22float2(b.h[2]);
            float2 f3 = __half22float2(a.h[3]), g3 = __half22float2(b.h[3]);
            s12[0] = f0.x + g0.x; s12[1] = f0.y + g0.y;
            s12[2] = f1.x + g1.x; s12[3] = f1.y + g1.y;
            s12[4] = f2.x + g2.x; s12[5] = f2.y + g2.y;
            s12[6] = f3.x + g3.x; s12[7] = f3.y + g3.y;
        }
        float4 o0, o1;
        o0.x = e0.x + rd * s12[0] + dinv * v[0];
        o0.y = e0.y + rd * s12[1] + dinv * v[1];
        o0.z = e0.z + rd * s12[2] + dinv * v[2];
        o0.w = e0.w + rd * s12[3] + dinv * v[3];
        o1.x = e1.x + rd * s12[4] + dinv * v[4];
        o1.y = e1.y + rd * s12[5] + dinv * v[5];
        o1.z = e1.z + rd * s12[6] + dinv * v[6];
        o1.w = e1.w + rd * s12[7] + dinv * v[7];
        float4* ap = (float4*)(d_acc + (size_t)node * 64 + ch * 8);
        ap[0] = o0;
        ap[1] = o1;
    }
}

// ---------------- KL over all rows: lane-per-row, W broadcast --------------
__global__ __launch_bounds__(256) void k_kl(const float* __restrict__ lin_w,
                                            const float* __restrict__ lin_b) {
    __shared__ float sW[2048];   // [d][t] d*32+t
    __shared__ float sB[64];
    __shared__ float wsum[8];
    int tid = threadIdx.x;
    for (int i = tid; i < 2048; i += 256) sW[i] = lin_w[i];
    if (tid < 64) sB[tid] = lin_b[tid];
    __syncthreads();
    int row = blockIdx.x * 256 + tid;
    float kl = 0.f;
    if (row < NN) {
        const float4* ar = (const float4*)(d_acc + (size_t)row * 64);
        float4 c0[8];
        #pragma unroll
        for (int i = 0; i < 8; i++) c0[i] = __ldg(ar + i);
        float sp[32];
        #pragma unroll
        for (int i = 0; i < 8; i++) {
            sp[4*i+0] = softplus_f(c0[i].x);
            sp[4*i+1] = softplus_f(c0[i].y);
            sp[4*i+2] = softplus_f(c0[i].z);
            sp[4*i+3] = softplus_f(c0[i].w);
        }
        #pragma unroll
        for (int half = 0; half < 2; half++) {
            if (half) {
                #pragma unroll
                for (int i = 0; i < 8; i++) c0[i] = __ldg(ar + 8 + i);
            }
            #pragma unroll
            for (int dq = 0; dq < 8; dq++) {
                float am[4] = {c0[dq].x, c0[dq].y, c0[dq].z, c0[dq].w};
                #pragma unroll
                for (int dj = 0; dj < 4; dj++) {
                    int d = half * 32 + dq * 4 + dj;
                    float s = sB[d] + 1e-8f;
                    #pragma unroll
                    for (int t4 = 0; t4 < 8; t4++) {
                        float4 w = *(const float4*)&sW[d * 32 + t4 * 4];
                        s += sp[4*t4] * w.x + sp[4*t4+1] * w.y
                           + sp[4*t4+2] * w.z + sp[4*t4+3] * w.w;
                    }
                    float k = -0.5f * (1.f + 2.f * s - am[dj] * am[dj] - expf(2.f * s));
                    if (isfinite(k)) kl += k;
                }
            }
        }
    }
    #pragma unroll
    for (int o = 16; o; o >>= 1) kl += __shfl_xor_sync(0xffffffffu, kl, o);
    if ((tid & 31) == 0) wsum[tid >> 5] = kl;
    __syncthreads();
    if (tid == 0) {
        float s = 0.f;
        #pragma unroll
        for (int i = 0; i < 8; i++) s += wsum[i];
        atomicAdd(&d_sums[0], (double)s);
    }
}

__global__ void k_bpr_emb(const float* __restrict__ ue, const float* __restrict__ ie,
                          const int* __restrict__ users, const int* __restrict__ pos,
                          const int* __restrict__ neg) {
    __shared__ float sb[8], se[8];
    int w = threadIdx.x >> 5, lane = threadIdx.x & 31;
    int b = blockIdx.x * 8 + w;
    float bpr = 0.f, emb = 0.f;
    {
        int u = users[b], pi = pos[b], ni = neg[b];
        float u0 = d_acc[u * 64 + lane],         u1 = d_acc[u * 64 + 32 + lane];
        float p0 = d_acc[(NU + pi) * 64 + lane], p1 = d_acc[(NU + pi) * 64 + 32 + lane];
        float n0 = d_acc[(NU + ni) * 64 + lane], n1 = d_acc[(NU + ni) * 64 + 32 + lane];
        float dsc = (u0 * n0 + u1 * n1) - (u0 * p0 + u1 * p1);
        float r0 = ue[u * 64 + lane],  r1 = ue[u * 64 + 32 + lane];
        float q0 = ie[pi * 64 + lane], q1 = ie[pi * 64 + 32 + lane];
        float m0 = ie[ni * 64 + lane], m1 = ie[ni * 64 + 32 + lane];
        float sq = r0 * r0 + r1 * r1 + q0 * q0 + q1 * q1 + m0 * m0 + m1 * m1;
        #pragma unroll
        for (int o = 16; o; o >>= 1) {
            dsc += __shfl_xor_sync(0xffffffffu, dsc, o);
            sq  += __shfl_xor_sync(0xffffffffu, sq, o);
        }
        if (lane == 0) { bpr = softplus_f(dsc); emb = sq; }
    }
    if (lane == 0) { sb[w] = bpr; se[w] = emb; }
    __syncthreads();
    if (threadIdx.x == 0) {
        float s1 = 0.f, s2 = 0.f;
        for (int i = 0; i < 8; i++) { s1 += sb[i]; s2 += se[i]; }
        atomicAdd(&d_sums[1], (double)s1);
        atomicAdd(&d_sums[2], (double)s2);
    }
}

// ---------------- build CL rows: one warp per sample -----------------------
__global__ __launch_bounds__(128) void k_build_cl(
        const float* __restrict__ u_int_w, const float* __restrict__ i_int_w,
        const float* __restrict__ lin_w, const float* __restrict__ lin_b,
        const float* __restrict__ eps,
        const int* __restrict__ users, const int* __restrict__ pos) {
    __shared__ float sI[64 * 129];   // intent [d][k], pitch 129
    __shared__ float sW[64 * 33];    // lin_w  [d][t], pitch 33
    int tid = threadIdx.x;
    int s = blockIdx.y;
    const float* intent = s ? i_int_w : u_int_w;
    for (int i = tid; i < 8192; i += 128)
        sI[(i >> 7) * 129 + (i & 127)] = intent[i];
    for (int i = tid; i < 2048; i += 128)
        sW[(i >> 5) * 33 + (i & 31)] = lin_w[i];
    __syncthreads();

    int wid = tid >> 5, lane = tid & 31;
    float bb0 = __ldg(lin_b + lane), bb1 = __ldg(lin_b + 32 + lane);

    for (int it = 0; it < 4; it++) {
        int b = blockIdx.x * 16 + wid * 4 + it;
        int r = s ? (NU + pos[b]) : users[b];
        float a0 = d_acc[(size_t)r * 64 + lane];
        float a1 = d_acc[(size_t)r * 64 + 32 + lane];

        float lg0 = 0.f, lg1 = 0.f, lg2 = 0.f, lg3 = 0.f;
        #pragma unroll
        for (int d = 0; d < 64; d++) {
            float ad = __shfl_sync(0xffffffffu, (d < 32) ? a0 : a1, d & 31);
            const float* row = &sI[d * 129 + lane];
            lg0 += ad * row[0];
            lg1 += ad * row[32];
            lg2 += ad * row[64];
            lg3 += ad * row[96];
        }
        float mx = fmaxf(fmaxf(lg0, lg1), fmaxf(lg2, lg3));
        #pragma unroll
        for (int o = 16; o; o >>= 1) mx = fmaxf(mx, __shfl_xor_sync(0xffffffffu, mx, o));
        float p0 = expf(lg0 - mx), p1 = expf(lg1 - mx), p2 = expf(lg2 - mx), p3 = expf(lg3 - mx);
        float ps = p0 + p1 + p2 + p3;
        #pragma unroll
        for (int o = 16; o; o >>= 1) ps += __shfl_xor_sync(0xffffffffu, ps, o);
        float inv = 1.f / ps;
        p0 *= inv; p1 *= inv; p2 *= inv; p3 *= inv;

        float ov0 = 0.f, ov1 = 0.f;
        const float* r0p = &sI[lane * 129];
        const float* r1p = &sI[(lane + 32) * 129];
        #pragma unroll
        for (int k = 0; k < 32; k++) {
            float q0 = __shfl_sync(0xffffffffu, p0, k);
            float q1 = __shfl_sync(0xffffffffu, p1, k);
            float q2 = __shfl_sync(0xffffffffu, p2, k);
            float q3 = __shfl_sync(0xffffffffu, p3, k);
            ov0 += q0 * r0p[k] + q1 * r0p[32 + k] + q2 * r0p[64 + k] + q3 * r0p[96 + k];
            ov1 += q0 * r1p[k] + q1 * r1p[32 + k] + q2 * r1p[64 + k] + q3 * r1p[96 + k];
        }

        float sp = softplus_f(a0);
        float sd0 = 0.f, sd1 = 0.f;
        const float* w0p = &sW[lane * 33];
        const float* w1p = &sW[(lane + 32) * 33];
        #pragma unroll
        for (int t = 0; t < 32; t++) {
            float spt = __shfl_sync(0xffffffffu, sp, t);
            sd0 += spt * w0p[t];
            sd1 += spt * w1p[t];
        }
        sd0 += bb0 + 1e-8f;
        sd1 += bb1 + 1e-8f;
        float g0 = a0 + __ldg(eps + (size_t)r * 64 + lane) * sd0;
        float g1 = a1 + __ldg(eps + (size_t)r * 64 + 32 + lane) * sd1;

        float gn = g0 * g0 + g1 * g1;
        float on = ov0 * ov0 + ov1 * ov1;
        #pragma unroll
        for (int o = 16; o; o >>= 1) {
            gn += __shfl_xor_sync(0xffffffffu, gn, o);
            on += __shfl_xor_sync(0xffffffffu, on, o);
        }
        gn = rsqrtf(gn); on = rsqrtf(on);
        g0 *= gn; g1 *= gn; ov0 *= on; ov1 *= on;
        float pd = g0 * ov0 + g1 * ov1;
        #pragma unroll
        for (int o = 16; o; o >>= 1) pd += __shfl_xor_sync(0xffffffffu, pd, o);

        size_t ob = (size_t)(s * BB + b) * 64;
        d_genH[ob + lane] = __float2half(g0);
        d_genH[ob + 32 + lane] = __float2half(g1);
        d_intH[ob + lane] = __float2half(ov0);
        d_intH[ob + 32 + lane] = __float2half(ov1);
        if (lane == 0) d_posS[s * BB + b] = pd;
    }
}

// ---------------- InfoNCE denominators via HMMA ----------------------------
__global__ __launch_bounds__(256, 1) void k_infonce_mma() {
    __shared__ __align__(16) __half sA[128 * 64];
    __shared__ __align__(16) __half sB[128 * 64];
    int s = blockIdx.z;
    int r0 = blockIdx.x * 128;
    int c0 = blockIdx.y * 128;
    const uint4* __restrict__ A  = (const uint4*)(d_genH + (size_t)s * BB * 64);
    const uint4* __restrict__ Bm = (const uint4*)(d_intH + (size_t)s * BB * 64);
    int tid = threadIdx.x;
    unsigned baseA = smem_u32(sA), baseB = smem_u32(sB);

    for (int i = tid; i < 1024; i += 256) {
        int r = i >> 3, c = i & 7;
        unsigned off = (unsigned)(r * 128 + c * 16);
        off ^= (unsigned)((r & 7) << 4);
        *(uint4*)((char*)sA + off) = __ldg(A  + (size_t)(r0 + r) * 8 + c);
        *(uint4*)((char*)sB + off) = __ldg(Bm + (size_t)(c0 + r) * 8 + c);
    }
    __syncthreads();

    int wid = tid >> 5, lane = tid & 31;
    int wr = wid >> 2, wc = wid & 3;
    float acc[4][4][4];
    #pragma unroll
    for (int i = 0; i < 4; i++)
        #pragma unroll
        for (int j = 0; j < 4; j++)
            #pragma unroll
            for (int q = 0; q < 4; q++) acc[i][j][q] = 0.f;

    int selA = lane >> 3, rinA = lane & 7;
    #pragma unroll
    for (int kc = 0; kc < 64; kc += 16) {
        unsigned af[4][4], bf[4][2];
        #pragma unroll
        for (int mi = 0; mi < 4; mi++) {
            int m = wr * 64 + mi * 16 + (selA & 1) * 8 + rinA;
            unsigned off = (unsigned)(m * 128 + kc * 2 + (selA >> 1) * 16);
            off ^= (unsigned)((m & 7) << 4);
            ldsm_x4(af[mi][0], af[mi][1], af[mi][2], af[mi][3], baseA + off);
        }
        #pragma unroll
        for (int ni = 0; ni < 4; ni++) {
            int n = wc * 32 + ni * 8 + rinA;
            unsigned off = (unsigned)(n * 128 + kc * 2 + ((lane >> 3) & 1) * 16);
            off ^= (unsigned)((n & 7) << 4);
            ldsm_x2(bf[ni][0], bf[ni][1], baseB + off);
        }
        #pragma unroll
        for (int mi = 0; mi < 4; mi++)
            #pragma unroll
            for (int ni = 0; ni < 4; ni++)
                mma16816(acc[mi][ni], af[mi][0], af[mi][1], af[mi][2], af[mi][3],
                         bf[ni][0], bf[ni][1]);
    }

    int quad = lane & 3, rr = lane >> 2;
    #pragma unroll
    for (int mi = 0; mi < 4; mi++) {
        float s0 = 0.f, s1 = 0.f;
        #pragma unroll
        for (int ni = 0; ni < 4; ni++) {
            s0 += __expf(acc[mi][ni][0] * 5.0f) + __expf(acc[mi][ni][1] * 5.0f);
            s1 += __expf(acc[mi][ni][2] * 5.0f) + __expf(acc[mi][ni][3] * 5.0f);
        }
        s0 += __shfl_xor_sync(0xffffffffu, s0, 1);
        s0 += __shfl_xor_sync(0xffffffffu, s0, 2);
        s1 += __shfl_xor_sync(0xffffffffu, s1, 1);
        s1 += __shfl_xor_sync(0xffffffffu, s1, 2);
        if (quad == 0) {
            int row = r0 + wr * 64 + mi * 16 + rr;
            atomicAdd(&d_negS[s * BB + row], s0);
            atomicAdd(&d_negS[s * BB + row + 8], s1);
        }
    }
}

__global__ void k_final(const float* __restrict__ ui, const float* __restrict__ ii,
                        float* __restrict__ out) {
    __shared__ double sh[256];
    __shared__ double sh2[256];
    int tid = threadIdx.x;
    double isum = 0.0, clsum = 0.0;
    for (int i = tid; i < 8192; i += 256) {
        float a = ui[i], b2 = ii[i];
        isum += (double)a * a + (double)b2 * b2;
    }
    for (int i = tid; i < 2 * BB; i += 256) {
        float ng = d_negS[i];
        d_negS[i] = 0.f;                       // recycle for next replay
        float p  = expf(d_posS[i] * 5.0f);
        clsum += -(double)logf(p / (ng + 1e-8f) + 1e-8f);
    }
    sh[tid] = isum; sh2[tid] = clsum;
    __syncthreads();
    for (int o = 128; o; o >>= 1) {
        if (tid < o) { sh[tid] += sh[tid + o]; sh2[tid] += sh2[tid + o]; }
        __syncthreads();
    }
    if (tid == 0) {
        double kl = d_sums[0], bpr = d_sums[1], emb = d_sums[2];
        out[0] = (float)(bpr / 4096.0 + 0.01 * (kl / 150000.0));
        out[1] = (float)(0.1 * (sh2[0] / 4096.0));
        out[2] = (float)(1e-5 * emb);
        out[3] = (float)(1e-5 * sh[0]);
        d_sums[0] = 0.0; d_sums[1] = 0.0; d_sums[2] = 0.0;   // recycle
        d_cursor = 0;                                        // recycle
    }
}

// ---------------- launch ---------------------------------------------------
extern "C" void kernel_launch(void* const* d_in, const int* in_sizes, int n_in,
                              void* d_out, int out_size) {
    (void)n_in; (void)out_size;
    const float* user_emb = (const float*)d_in[0];
    const float* item_emb = (const float*)d_in[1];
    const float* user_int = (const float*)d_in[2];
    const float* item_int = (const float*)d_in[3];
    const float* lin_w    = (const float*)d_in[4];
    const float* lin_b    = (const float*)d_in[5];
    const float* eps      = (const float*)d_in[6];
    const int*   h        = (const int*)d_in[7];
    const int*   t        = (const int*)d_in[8];
    const int*   users    = (const int*)d_in[9];
    const int*   pos      = (const int*)d_in[10];
    const int*   neg      = (const int*)d_in[11];
    int E = in_sizes[7];
    float* out = (float*)d_out;

    int e4b = ((E >> 2) + 255) / 256;
    k_count<<<e4b, 256>>>((const int4*)h, h, E);
    k_scanfill<<<NBLK, 256>>>((const float4*)user_emb, (const float4*)item_emb);
    k_bin<<<e4b, 256>>>((const int4*)h, (const int4*)t, h, t, E);

    int gb = NN * 32 / 256;
    k_gather<0><<<gb, 256>>>((const float4*)user_emb, (const float4*)item_emb);
    k_gather<1><<<gb, 256>>>((const float4*)user_emb, (const float4*)item_emb);
    k_gather<2><<<gb, 256>>>((const float4*)user_emb, (const float4*)item_emb);

    k_kl<<<NBLK, 256>>>(lin_w, lin_b);
    k_bpr_emb<<<BB / 8, 256>>>(user_emb, item_emb, users, pos, neg);
    k_build_cl<<<dim3(BB / 16, 2), 128>>>(user_int, item_int, lin_w, lin_b, eps, users, pos);
    k_infonce_mma<<<dim3(32, 32, 2), 256>>>();
    k_final<<<1, 256>>>(user_int, item_int, out);
}